// round 2
// baseline (speedup 1.0000x reference)
#include <cuda_runtime.h>
#include <cuda_bf16.h>
#include <cstdint>

// Problem constants (fixed by the dataset)
#define MAXN 101024
#define MAXE 2000000
#define FEAT 1024
#define H0 128

// ---------------- scratch (device globals; no allocation allowed) ----------
__device__ float g_h [(size_t)MAXN * H0];   // node features (ping)
__device__ float g_hw[(size_t)MAXN * H0];   // h @ W       (pong)
__device__ float g_dinv[MAXN];
__device__ int   g_cnt[MAXN];
__device__ int   g_rowoff[MAXN + 1];
__device__ int   g_cursor[MAXN];
__device__ int   g_esrc[MAXE];
__device__ float g_enorm[MAXE];

// ---------------- CSR construction ----------------------------------------
__global__ void zero_cnt_kernel(int n) {
    int i = blockIdx.x * blockDim.x + threadIdx.x;
    if (i < n) g_cnt[i] = 0;
}

__global__ void count_kernel(const int* __restrict__ dst, int E) {
    int i = blockIdx.x * blockDim.x + threadIdx.x;
    if (i < E) atomicAdd(&g_cnt[dst[i]], 1);
}

__global__ void dinv_kernel(int n) {
    int i = blockIdx.x * blockDim.x + threadIdx.x;
    if (i < n) g_dinv[i] = rsqrtf((float)(g_cnt[i] + 1));  // +1 self loop
}

// single-block exclusive scan over g_cnt -> g_rowoff / g_cursor
__global__ void scan_kernel(int n) {
    __shared__ int part[1024];
    int tid = threadIdx.x;
    int chunk = (n + 1023) >> 10;
    int beg = tid * chunk;
    int end = min(beg + chunk, n);
    int s = 0;
    for (int i = beg; i < end; i++) s += g_cnt[i];
    part[tid] = s;
    __syncthreads();
    for (int off = 1; off < 1024; off <<= 1) {
        int t = (tid >= off) ? part[tid - off] : 0;
        __syncthreads();
        part[tid] += t;
        __syncthreads();
    }
    int run = part[tid] - s;  // exclusive prefix
    for (int i = beg; i < end; i++) {
        g_rowoff[i] = run;
        g_cursor[i] = run;
        run += g_cnt[i];
    }
    if (tid == 1023) g_rowoff[n] = part[1023];
}

__global__ void fill_kernel(const int* __restrict__ src, const int* __restrict__ dst, int E) {
    int i = blockIdx.x * blockDim.x + threadIdx.x;
    if (i >= E) return;
    int s = src[i], d = dst[i];
    int p = atomicAdd(&g_cursor[d], 1);
    g_esrc[p]  = s;
    g_enorm[p] = g_dinv[s] * g_dinv[d];
}

// ---------------- SGEMM: C[nrows, BN] = A[nrows, K] @ W[K, BN] (+bias) -----
// 128x BN tile per block, 256 threads, 8 x (BN/16) micro-tile per thread.
// Projection uses two weight/bias sets selected by row (< userRows -> set 0).
template <int BN>
__global__ void __launch_bounds__(256, 2) sgemm_kernel(
    const float* __restrict__ A,
    const float* __restrict__ W0, const float* __restrict__ W1,
    const float* __restrict__ b0, const float* __restrict__ b1,
    float* __restrict__ C, int nrows, int K, int userRows)
{
    constexpr int TN = BN / 16;
    __shared__ float As[16][132];     // padded, keeps 16B alignment (132*4 % 16 == 0)
    __shared__ float Bs[16][BN];

    int r0 = blockIdx.x * 128;
    const float* W    = (r0 < userRows) ? W0 : W1;
    const float* bias = (r0 < userRows) ? b0 : b1;

    int tid = threadIdx.x;
    int tx = tid & 15;          // 0..15 -> col group
    int ty = tid >> 4;          // 0..15 -> row group

    float acc[8][TN];
#pragma unroll
    for (int i = 0; i < 8; i++)
#pragma unroll
        for (int j = 0; j < TN; j++) acc[i][j] = 0.f;

    for (int k0 = 0; k0 < K; k0 += 16) {
        // A tile: 128 rows x 16 k = 512 float4, 2 per thread, stored transposed
#pragma unroll
        for (int p = 0; p < 2; p++) {
            int idx = tid + p * 256;          // 0..511
            int row = idx >> 2;               // 0..127
            int q   = (idx & 3) * 4;          // 0,4,8,12
            int grow = r0 + row;
            float4 v = make_float4(0.f, 0.f, 0.f, 0.f);
            if (grow < nrows)
                v = *(const float4*)(A + (size_t)grow * K + k0 + q);
            As[q + 0][row] = v.x;
            As[q + 1][row] = v.y;
            As[q + 2][row] = v.z;
            As[q + 3][row] = v.w;
        }
        // W tile: 16 x BN floats = (16*BN/4) float4
#pragma unroll
        for (int p = 0; p < BN / 64; p++) {
            int idx = tid + p * 256;
            int kk = idx / (BN / 4);
            int c4 = (idx % (BN / 4)) * 4;
            *(float4*)&Bs[kk][c4] = *(const float4*)(W + (size_t)(k0 + kk) * BN + c4);
        }
        __syncthreads();

#pragma unroll
        for (int k = 0; k < 16; k++) {
            float a[8], b[TN];
            float4 a0 = *(const float4*)&As[k][ty * 8];
            float4 a1 = *(const float4*)&As[k][ty * 8 + 4];
            a[0] = a0.x; a[1] = a0.y; a[2] = a0.z; a[3] = a0.w;
            a[4] = a1.x; a[5] = a1.y; a[6] = a1.z; a[7] = a1.w;
#pragma unroll
            for (int j4 = 0; j4 < TN; j4 += 4) {
                float4 bb4 = *(const float4*)&Bs[k][tx * TN + j4];
                b[j4 + 0] = bb4.x; b[j4 + 1] = bb4.y; b[j4 + 2] = bb4.z; b[j4 + 3] = bb4.w;
            }
#pragma unroll
            for (int i = 0; i < 8; i++)
#pragma unroll
                for (int j = 0; j < TN; j++) acc[i][j] += a[i] * b[j];
        }
        __syncthreads();
    }

    // epilogue
#pragma unroll
    for (int i = 0; i < 8; i++) {
        int grow = r0 + ty * 8 + i;
        if (grow >= nrows) continue;
#pragma unroll
        for (int j4 = 0; j4 < TN; j4 += 4) {
            int c = tx * TN + j4;
            float4 v;
            v.x = acc[i][j4 + 0];
            v.y = acc[i][j4 + 1];
            v.z = acc[i][j4 + 2];
            v.w = acc[i][j4 + 3];
            if (bias) {
                v.x += bias[c + 0]; v.y += bias[c + 1];
                v.z += bias[c + 2]; v.w += bias[c + 3];
            }
            *(float4*)(C + (size_t)grow * BN + c) = v;
        }
    }
}

// ---------------- CSR aggregation: out[d] = relu?(hw[d]*dinv[d]^2 +
//                      sum_e hw[src_e]*norm_e + bias) ------------------------
// one warp per dst node; lane covers HD/32 contiguous columns (vectorized)
template <int HD, bool RELU>
__global__ void aggregate_kernel(const float* __restrict__ hw,
                                 const float* __restrict__ bias,
                                 float* __restrict__ out, int n)
{
    constexpr int V = HD / 32;    // 4 or 2
    int gw = (blockIdx.x * blockDim.x + threadIdx.x) >> 5;
    if (gw >= n) return;
    int lane = threadIdx.x & 31;

    float acc[V];
    float di = g_dinv[gw];
    float sl = di * di;

    if (V == 4) {
        float4 r = *(const float4*)(hw + (size_t)gw * HD + lane * 4);
        acc[0] = r.x * sl; acc[1] = r.y * sl; acc[2] = r.z * sl; acc[3] = r.w * sl;
    } else {
        float2 r = *(const float2*)(hw + (size_t)gw * HD + lane * 2);
        acc[0] = r.x * sl; acc[1] = r.y * sl;
    }

    int e   = g_rowoff[gw];
    int end = g_rowoff[gw + 1];
    for (; e < end; e++) {
        int   s  = __ldg(&g_esrc[e]);
        float nm = __ldg(&g_enorm[e]);
        if (V == 4) {
            float4 r = *(const float4*)(hw + (size_t)s * HD + lane * 4);
            acc[0] += r.x * nm; acc[1] += r.y * nm;
            acc[2] += r.z * nm; acc[3] += r.w * nm;
        } else {
            float2 r = *(const float2*)(hw + (size_t)s * HD + lane * 2);
            acc[0] += r.x * nm; acc[1] += r.y * nm;
        }
    }

#pragma unroll
    for (int v = 0; v < V; v++) {
        float val = acc[v] + bias[lane * V + v];
        if (RELU) val = fmaxf(val, 0.f);
        acc[v] = val;
    }
    if (V == 4) {
        float4 o; o.x = acc[0]; o.y = acc[1]; o.z = acc[2]; o.w = acc[3];
        *(float4*)(out + (size_t)gw * HD + lane * 4) = o;
    } else {
        float2 o; o.x = acc[0]; o.y = acc[1];
        *(float2*)(out + (size_t)gw * HD + lane * 2) = o;
    }
}

// ---------------- launch ----------------------------------------------------
extern "C" void kernel_launch(void* const* d_in, const int* in_sizes, int n_in,
                              void* d_out, int out_size)
{
    const float* x  = (const float*)d_in[0];
    const int*   ei = (const int*)  d_in[1];
    const float* Wu = (const float*)d_in[2];
    const float* bu = (const float*)d_in[3];
    const float* Wb = (const float*)d_in[4];
    const float* bb = (const float*)d_in[5];
    const float* W1 = (const float*)d_in[6];
    const float* b1 = (const float*)d_in[7];
    const float* W2 = (const float*)d_in[8];
    const float* b2 = (const float*)d_in[9];
    const float* W3 = (const float*)d_in[10];
    const float* b3 = (const float*)d_in[11];

    const int N = in_sizes[0] / FEAT;     // 101024
    const int E = in_sizes[1] / 2;        // 2000000
    const int userRows = 1024;

    float *h_ptr, *hw_ptr;
    cudaGetSymbolAddress((void**)&h_ptr,  g_h);
    cudaGetSymbolAddress((void**)&hw_ptr, g_hw);

    const int* src = ei;
    const int* dst = ei + E;

    // 1) degree / CSR build
    zero_cnt_kernel<<<(N + 255) / 256, 256>>>(N);
    count_kernel<<<(E + 255) / 256, 256>>>(dst, E);
    dinv_kernel<<<(N + 255) / 256, 256>>>(N);
    scan_kernel<<<1, 1024>>>(N);
    fill_kernel<<<(E + 255) / 256, 256>>>(src, dst, E);

    int gemmBlocks = (N + 127) / 128;
    int aggBlocks  = (N + 7) / 8;         // 8 warps / block

    // 2) projection: h = x @ (Wu|Wb) + (bu|bb)
    sgemm_kernel<128><<<gemmBlocks, 256>>>(x, Wu, Wb, bu, bb, h_ptr, N, FEAT, userRows);

    // 3) layer 1: hw = h @ W1 ; h = relu(agg(hw) + b1)
    sgemm_kernel<128><<<gemmBlocks, 256>>>(h_ptr, W1, W1, nullptr, nullptr, hw_ptr, N, H0, 0x7fffffff);
    aggregate_kernel<128, true><<<aggBlocks, 256>>>(hw_ptr, b1, h_ptr, N);

    // 4) layer 2
    sgemm_kernel<128><<<gemmBlocks, 256>>>(h_ptr, W2, W2, nullptr, nullptr, hw_ptr, N, H0, 0x7fffffff);
    aggregate_kernel<128, true><<<aggBlocks, 256>>>(hw_ptr, b2, h_ptr, N);

    // 5) layer 3 (out dim 64, no relu) -> d_out
    sgemm_kernel<64><<<gemmBlocks, 256>>>(h_ptr, W3, W3, nullptr, nullptr, hw_ptr, N, H0, 0x7fffffff);
    aggregate_kernel<64, false><<<aggBlocks, 256>>>(hw_ptr, b3, (float*)d_out, N);
}

// round 5
// speedup vs baseline: 1.8476x; 1.8476x over previous
#include <cuda_runtime.h>
#include <cuda_bf16.h>
#include <cstdint>

// Problem constants (fixed by the dataset)
#define MAXN 101024
#define MAXE 2000000
#define FEAT 1024
#define H0 128

// ---------------- scratch (device globals; no allocation allowed) ----------
__device__ float g_h [(size_t)MAXN * H0];   // node features (ping)
__device__ float g_hw[(size_t)MAXN * H0];   // h @ W       (pong)
__device__ float g_dinv[MAXN];
__device__ int   g_cnt[MAXN];
__device__ int   g_rowoff[MAXN + 1];
__device__ int   g_cursor[MAXN];
__device__ int   g_rowtmp[MAXN];
__device__ int   g_bsum[128];
__device__ int   g_boff[128];
__device__ int   g_esrc[MAXE];
__device__ float g_enorm[MAXE];

// bf16 hi/lo weight buffers, transposed to B-format [n][k]
__device__ __nv_bfloat16 g_bhi_u[128 * 1024];
__device__ __nv_bfloat16 g_blo_u[128 * 1024];
__device__ __nv_bfloat16 g_bhi_b[128 * 1024];
__device__ __nv_bfloat16 g_blo_b[128 * 1024];
__device__ __nv_bfloat16 g_bhi_1[128 * 128];
__device__ __nv_bfloat16 g_blo_1[128 * 128];
__device__ __nv_bfloat16 g_bhi_2[128 * 128];
__device__ __nv_bfloat16 g_blo_2[128 * 128];
__device__ __nv_bfloat16 g_bhi_3[64 * 128];
__device__ __nv_bfloat16 g_blo_3[64 * 128];

// ---------------- CSR construction ----------------------------------------
__global__ void zero_cnt_kernel(int n) {
    int i = blockIdx.x * blockDim.x + threadIdx.x;
    if (i < n) g_cnt[i] = 0;
}

__global__ void count_kernel(const int* __restrict__ dst, int E) {
    int i = blockIdx.x * blockDim.x + threadIdx.x;
    if (i < E) atomicAdd(&g_cnt[dst[i]], 1);
}

__global__ void dinv_kernel(int n) {
    int i = blockIdx.x * blockDim.x + threadIdx.x;
    if (i < n) g_dinv[i] = rsqrtf((float)(g_cnt[i] + 1));  // +1 self loop
}

// multi-block scan: per-block exclusive scan + block sums
__global__ void scan_block_kernel(int n) {
    __shared__ int sh[1024];
    int tid = threadIdx.x;
    int i = blockIdx.x * 1024 + tid;
    int v = (i < n) ? g_cnt[i] : 0;
    sh[tid] = v;
    __syncthreads();
    for (int off = 1; off < 1024; off <<= 1) {
        int t = (tid >= off) ? sh[tid - off] : 0;
        __syncthreads();
        sh[tid] += t;
        __syncthreads();
    }
    if (i < n) g_rowtmp[i] = sh[tid] - v;   // exclusive within block
    if (tid == 1023) g_bsum[blockIdx.x] = sh[1023];
}

__global__ void scan_bsum_kernel(int nb, int n) {
    __shared__ int sh[128];
    int tid = threadIdx.x;
    int v = (tid < nb) ? g_bsum[tid] : 0;
    sh[tid] = v;
    __syncthreads();
    for (int off = 1; off < 128; off <<= 1) {
        int t = (tid >= off) ? sh[tid - off] : 0;
        __syncthreads();
        sh[tid] += t;
        __syncthreads();
    }
    if (tid < nb) g_boff[tid] = sh[tid] - v;
    if (tid == 127) g_rowoff[n] = sh[127];
}

__global__ void scan_add_kernel(int n) {
    int i = blockIdx.x * blockDim.x + threadIdx.x;
    if (i >= n) return;
    int val = g_rowtmp[i] + g_boff[i >> 10];
    g_rowoff[i] = val;
    g_cursor[i] = val;
}

__global__ void fill_kernel(const int* __restrict__ src, const int* __restrict__ dst, int E) {
    int i = blockIdx.x * blockDim.x + threadIdx.x;
    if (i >= E) return;
    int s = src[i], d = dst[i];
    int p = atomicAdd(&g_cursor[d], 1);
    g_esrc[p]  = s;
    g_enorm[p] = g_dinv[s] * g_dinv[d];
}

// -------- weight convert: W[K][NC] fp32 -> B-format [n][k] bf16 hi/lo -------
__global__ void convw_kernel(const float* __restrict__ W,
                             __nv_bfloat16* __restrict__ bhi,
                             __nv_bfloat16* __restrict__ blo, int K, int NC) {
    int idx = blockIdx.x * blockDim.x + threadIdx.x;
    if (idx >= K * NC) return;
    int k = idx / NC, n = idx % NC;
    float v = W[idx];
    __nv_bfloat16 h = __float2bfloat16(v);
    float r = v - __bfloat162float(h);
    bhi[n * K + k] = h;
    blo[n * K + k] = __float2bfloat16(r);
}

// ---------------- HMMA (mma.sync) split-bf16 GEMM ---------------------------
// C[nrows, NCOL] = A[nrows, KTOT] @ W via bf16 hi/lo (3 passes), fp32 acc.
// CTA: 128 x NCOL tile, 256 threads (8 warps: 4 in M x 2 in N), BK = 32.
__device__ __forceinline__ void mma16816(float* c, const uint32_t* a, const uint32_t* b) {
    asm volatile(
        "mma.sync.aligned.m16n8k16.row.col.f32.bf16.bf16.f32 "
        "{%0,%1,%2,%3}, {%4,%5,%6,%7}, {%8,%9}, {%0,%1,%2,%3};\n"
        : "+f"(c[0]), "+f"(c[1]), "+f"(c[2]), "+f"(c[3])
        : "r"(a[0]), "r"(a[1]), "r"(a[2]), "r"(a[3]), "r"(b[0]), "r"(b[1]));
}

__device__ __forceinline__ void split_f4(float4 v, uint2& hi, uint2& lo) {
    __nv_bfloat16 hx = __float2bfloat16(v.x), hy = __float2bfloat16(v.y);
    __nv_bfloat16 hz = __float2bfloat16(v.z), hw = __float2bfloat16(v.w);
    float rx = v.x - __bfloat162float(hx), ry = v.y - __bfloat162float(hy);
    float rz = v.z - __bfloat162float(hz), rw = v.w - __bfloat162float(hw);
    uint32_t hxu = __bfloat16_as_ushort(hx), hyu = __bfloat16_as_ushort(hy);
    uint32_t hzu = __bfloat16_as_ushort(hz), hwu = __bfloat16_as_ushort(hw);
    uint32_t lxu = __bfloat16_as_ushort(__float2bfloat16(rx));
    uint32_t lyu = __bfloat16_as_ushort(__float2bfloat16(ry));
    uint32_t lzu = __bfloat16_as_ushort(__float2bfloat16(rz));
    uint32_t lwu = __bfloat16_as_ushort(__float2bfloat16(rw));
    hi = make_uint2(hxu | (hyu << 16), hzu | (hwu << 16));
    lo = make_uint2(lxu | (lyu << 16), lzu | (lwu << 16));
}

template <int NCOL>
__global__ void __launch_bounds__(256, 2) gemm_mma_kernel(
    const float* __restrict__ A,
    const __nv_bfloat16* __restrict__ Bhi0, const __nv_bfloat16* __restrict__ Blo0,
    const __nv_bfloat16* __restrict__ Bhi1, const __nv_bfloat16* __restrict__ Blo1,
    const float* __restrict__ bias0, const float* __restrict__ bias1,
    float* __restrict__ C, int nrows, int KTOT, int userRows)
{
    constexpr int STR = 40;               // smem row stride in halves (bank-safe)
    constexpr int WN  = NCOL / 2;         // per-warp N extent (64 or 32)
    constexpr int NF  = WN / 8;           // n-fragments per warp (8 or 4)

    __shared__ uint16_t As_hi[128 * STR];
    __shared__ uint16_t As_lo[128 * STR];
    __shared__ uint16_t Bs_hi[NCOL * STR];
    __shared__ uint16_t Bs_lo[NCOL * STR];

    const int tid  = threadIdx.x;
    const int wid  = tid >> 5;
    const int lane = tid & 31;
    const int wm   = wid & 3;             // warp m index (0..3) -> rows wm*32
    const int wn   = wid >> 2;            // warp n index (0..1) -> cols wn*WN
    const int g    = lane >> 2;           // 0..7
    const int t    = lane & 3;            // 0..3

    const int r0   = blockIdx.x * 128;
    const bool set0 = (r0 < userRows);
    const __nv_bfloat16* Bhi = set0 ? Bhi0 : Bhi1;
    const __nv_bfloat16* Blo = set0 ? Blo0 : Blo1;
    const float* bias = set0 ? bias0 : bias1;

    float acc[2][NF][4];
#pragma unroll
    for (int mf = 0; mf < 2; mf++)
#pragma unroll
        for (int nf = 0; nf < NF; nf++)
#pragma unroll
            for (int i = 0; i < 4; i++) acc[mf][nf][i] = 0.f;

    const int nchunk = KTOT >> 5;         // BK = 32
    for (int c = 0; c < nchunk; c++) {
        const int k0 = c << 5;

        // ---- A chunk: 128 rows x 32 fp32 -> bf16 hi/lo into smem ----
        // 1024 float4 total, 4 per thread
#pragma unroll
        for (int i = 0; i < 4; i++) {
            int idx = tid + i * 256;          // 0..1023
            int row = idx >> 3;               // 8 float4 per row
            int c4  = (idx & 7) << 2;         // 0,4,...,28 (half-index)
            float4 v = make_float4(0.f, 0.f, 0.f, 0.f);
            if (r0 + row < nrows)
                v = *(const float4*)(A + (size_t)(r0 + row) * KTOT + k0 + c4);
            uint2 hi, lo;
            split_f4(v, hi, lo);
            *(uint2*)&As_hi[row * STR + c4] = hi;
            *(uint2*)&As_lo[row * STR + c4] = lo;
        }
        // ---- B chunk: NCOL rows x 32 halves (hi & lo) ----
#pragma unroll
        for (int i = 0; i < NCOL / 64; i++) {
            int idx = tid + i * 256;          // < NCOL*4
            int n  = idx >> 2;
            int c8 = (idx & 3) << 3;          // 0,8,16,24
            *(uint4*)&Bs_hi[n * STR + c8] = *(const uint4*)(Bhi + (size_t)n * KTOT + k0 + c8);
            *(uint4*)&Bs_lo[n * STR + c8] = *(const uint4*)(Blo + (size_t)n * KTOT + k0 + c8);
        }
        __syncthreads();

        // ---- compute: 2 k16 steps, 3 MMA passes each ----
#pragma unroll
        for (int ks = 0; ks < 2; ks++) {
            uint32_t ah[2][4], al[2][4];
#pragma unroll
            for (int mf = 0; mf < 2; mf++) {
                int rb = (wm * 32 + mf * 16 + g) * STR + ks * 16 + t * 2;
                int r8 = rb + 8 * STR;
                ah[mf][0] = *(const uint32_t*)&As_hi[rb];
                ah[mf][1] = *(const uint32_t*)&As_hi[r8];
                ah[mf][2] = *(const uint32_t*)&As_hi[rb + 8];
                ah[mf][3] = *(const uint32_t*)&As_hi[r8 + 8];
                al[mf][0] = *(const uint32_t*)&As_lo[rb];
                al[mf][1] = *(const uint32_t*)&As_lo[r8];
                al[mf][2] = *(const uint32_t*)&As_lo[rb + 8];
                al[mf][3] = *(const uint32_t*)&As_lo[r8 + 8];
            }
#pragma unroll
            for (int nf = 0; nf < NF; nf++) {
                int bb = (wn * WN + nf * 8 + g) * STR + ks * 16 + t * 2;
                uint32_t bh[2], bl[2];
                bh[0] = *(const uint32_t*)&Bs_hi[bb];
                bh[1] = *(const uint32_t*)&Bs_hi[bb + 8];
                bl[0] = *(const uint32_t*)&Bs_lo[bb];
                bl[1] = *(const uint32_t*)&Bs_lo[bb + 8];
#pragma unroll
                for (int mf = 0; mf < 2; mf++) {
                    mma16816(acc[mf][nf], ah[mf], bh);
                    mma16816(acc[mf][nf], ah[mf], bl);
                    mma16816(acc[mf][nf], al[mf], bh);
                }
            }
        }
        __syncthreads();
    }

    // ---- epilogue: acc -> C (+bias) ----
#pragma unroll
    for (int mf = 0; mf < 2; mf++) {
        int row = r0 + wm * 32 + mf * 16 + g;
#pragma unroll
        for (int nf = 0; nf < NF; nf++) {
            int col = wn * WN + nf * 8 + t * 2;
            float bx = bias ? bias[col] : 0.f;
            float by = bias ? bias[col + 1] : 0.f;
            if (row < nrows) {
                float2 v;
                v.x = acc[mf][nf][0] + bx;
                v.y = acc[mf][nf][1] + by;
                *(float2*)(C + (size_t)row * NCOL + col) = v;
            }
            if (row + 8 < nrows) {
                float2 v;
                v.x = acc[mf][nf][2] + bx;
                v.y = acc[mf][nf][3] + by;
                *(float2*)(C + (size_t)(row + 8) * NCOL + col) = v;
            }
        }
    }
}

// ---------------- CSR aggregation -------------------------------------------
template <int HD, bool RELU>
__global__ void aggregate_kernel(const float* __restrict__ hw,
                                 const float* __restrict__ bias,
                                 float* __restrict__ out, int n)
{
    constexpr int V = HD / 32;    // 4 or 2
    int gw = (blockIdx.x * blockDim.x + threadIdx.x) >> 5;
    if (gw >= n) return;
    int lane = threadIdx.x & 31;

    float acc[V];
    float di = g_dinv[gw];
    float sl = di * di;

    if (V == 4) {
        float4 r = *(const float4*)(hw + (size_t)gw * HD + lane * 4);
        acc[0] = r.x * sl; acc[1] = r.y * sl; acc[2] = r.z * sl; acc[3] = r.w * sl;
    } else {
        float2 r = *(const float2*)(hw + (size_t)gw * HD + lane * 2);
        acc[0] = r.x * sl; acc[1] = r.y * sl;
    }

    int e   = g_rowoff[gw];
    int end = g_rowoff[gw + 1];
    for (; e < end; e++) {
        int   s  = __ldg(&g_esrc[e]);
        float nm = __ldg(&g_enorm[e]);
        if (V == 4) {
            float4 r = *(const float4*)(hw + (size_t)s * HD + lane * 4);
            acc[0] += r.x * nm; acc[1] += r.y * nm;
            acc[2] += r.z * nm; acc[3] += r.w * nm;
        } else {
            float2 r = *(const float2*)(hw + (size_t)s * HD + lane * 2);
            acc[0] += r.x * nm; acc[1] += r.y * nm;
        }
    }

#pragma unroll
    for (int v = 0; v < V; v++) {
        float val = acc[v] + bias[lane * V + v];
        if (RELU) val = fmaxf(val, 0.f);
        acc[v] = val;
    }
    if (V == 4) {
        float4 o; o.x = acc[0]; o.y = acc[1]; o.z = acc[2]; o.w = acc[3];
        *(float4*)(out + (size_t)gw * HD + lane * 4) = o;
    } else {
        float2 o; o.x = acc[0]; o.y = acc[1];
        *(float2*)(out + (size_t)gw * HD + lane * 2) = o;
    }
}

// ---------------- launch ----------------------------------------------------
extern "C" void kernel_launch(void* const* d_in, const int* in_sizes, int n_in,
                              void* d_out, int out_size)
{
    const float* x  = (const float*)d_in[0];
    const int*   ei = (const int*)  d_in[1];
    const float* Wu = (const float*)d_in[2];
    const float* bu = (const float*)d_in[3];
    const float* Wb = (const float*)d_in[4];
    const float* bb = (const float*)d_in[5];
    const float* W1 = (const float*)d_in[6];
    const float* b1 = (const float*)d_in[7];
    const float* W2 = (const float*)d_in[8];
    const float* b2 = (const float*)d_in[9];
    const float* W3 = (const float*)d_in[10];
    const float* b3 = (const float*)d_in[11];

    const int N = in_sizes[0] / FEAT;     // 101024
    const int E = in_sizes[1] / 2;        // 2000000
    const int userRows = 1024;

    float *h_ptr, *hw_ptr;
    cudaGetSymbolAddress((void**)&h_ptr,  g_h);
    cudaGetSymbolAddress((void**)&hw_ptr, g_hw);

    __nv_bfloat16 *bhi_u, *blo_u, *bhi_b, *blo_b, *bhi_1, *blo_1, *bhi_2, *blo_2, *bhi_3, *blo_3;
    cudaGetSymbolAddress((void**)&bhi_u, g_bhi_u);
    cudaGetSymbolAddress((void**)&blo_u, g_blo_u);
    cudaGetSymbolAddress((void**)&bhi_b, g_bhi_b);
    cudaGetSymbolAddress((void**)&blo_b, g_blo_b);
    cudaGetSymbolAddress((void**)&bhi_1, g_bhi_1);
    cudaGetSymbolAddress((void**)&blo_1, g_blo_1);
    cudaGetSymbolAddress((void**)&bhi_2, g_bhi_2);
    cudaGetSymbolAddress((void**)&blo_2, g_blo_2);
    cudaGetSymbolAddress((void**)&bhi_3, g_bhi_3);
    cudaGetSymbolAddress((void**)&blo_3, g_blo_3);

    const int* src = ei;
    const int* dst = ei + E;

    // 1) degree / CSR build
    zero_cnt_kernel<<<(N + 255) / 256, 256>>>(N);
    count_kernel<<<(E + 255) / 256, 256>>>(dst, E);
    dinv_kernel<<<(N + 255) / 256, 256>>>(N);
    int nb = (N + 1023) / 1024;
    scan_block_kernel<<<nb, 1024>>>(N);
    scan_bsum_kernel<<<1, 128>>>(nb, N);
    scan_add_kernel<<<(N + 255) / 256, 256>>>(N);
    fill_kernel<<<(E + 255) / 256, 256>>>(src, dst, E);

    // 2) weight conversion (fp32 -> transposed bf16 hi/lo)
    convw_kernel<<<(FEAT * 128 + 255) / 256, 256>>>(Wu, bhi_u, blo_u, FEAT, 128);
    convw_kernel<<<(FEAT * 128 + 255) / 256, 256>>>(Wb, bhi_b, blo_b, FEAT, 128);
    convw_kernel<<<(128 * 128 + 255) / 256, 256>>>(W1, bhi_1, blo_1, 128, 128);
    convw_kernel<<<(128 * 128 + 255) / 256, 256>>>(W2, bhi_2, blo_2, 128, 128);
    convw_kernel<<<(128 * 64  + 255) / 256, 256>>>(W3, bhi_3, blo_3, 128, 64);

    int gemmBlocks = (N + 127) / 128;
    int aggBlocks  = (N + 7) / 8;         // 8 warps / block

    // 3) projection: h = x @ (Wu|Wb) + (bu|bb)
    gemm_mma_kernel<128><<<gemmBlocks, 256>>>(
        x, bhi_u, blo_u, bhi_b, blo_b, bu, bb, h_ptr, N, FEAT, userRows);

    // 4) layer 1: hw = h @ W1 ; h = relu(agg(hw) + b1)
    gemm_mma_kernel<128><<<gemmBlocks, 256>>>(
        h_ptr, bhi_1, blo_1, bhi_1, blo_1, nullptr, nullptr, hw_ptr, N, H0, 0x7fffffff);
    aggregate_kernel<128, true><<<aggBlocks, 256>>>(hw_ptr, b1, h_ptr, N);

    // 5) layer 2
    gemm_mma_kernel<128><<<gemmBlocks, 256>>>(
        h_ptr, bhi_2, blo_2, bhi_2, blo_2, nullptr, nullptr, hw_ptr, N, H0, 0x7fffffff);
    aggregate_kernel<128, true><<<aggBlocks, 256>>>(hw_ptr, b2, h_ptr, N);

    // 6) layer 3 (out dim 64, no relu) -> d_out
    gemm_mma_kernel<64><<<gemmBlocks, 256>>>(
        h_ptr, bhi_3, blo_3, bhi_3, blo_3, nullptr, nullptr, hw_ptr, N, H0, 0x7fffffff);
    aggregate_kernel<64, false><<<aggBlocks, 256>>>(hw_ptr, b3, (float*)d_out, N);
}

// round 6
// speedup vs baseline: 2.1027x; 1.1381x over previous
#include <cuda_runtime.h>
#include <cuda_bf16.h>
#include <cstdint>

// Problem constants (fixed by the dataset)
#define MAXN 101024
#define MAXE 2000000
#define FEAT 1024
#define H0 128

// ---------------- scratch (device globals; no allocation allowed) ----------
__device__ float g_h [(size_t)MAXN * H0];   // node features (ping)
__device__ float g_hw[(size_t)MAXN * H0];   // h @ W       (pong)
__device__ float g_dinv[MAXN];
__device__ int   g_cnt[MAXN];
__device__ int   g_rowoff[MAXN + 1];
__device__ int   g_cursor[MAXN];
__device__ int   g_rowtmp[MAXN];
__device__ int   g_bsum[128];
__device__ int   g_boff[128];
__device__ int   g_esrc[MAXE];
__device__ float g_enorm[MAXE];

// bf16 hi/lo weight buffers, transposed to B-format [n][k]
__device__ __nv_bfloat16 g_bhi_u[128 * 1024];
__device__ __nv_bfloat16 g_blo_u[128 * 1024];
__device__ __nv_bfloat16 g_bhi_b[128 * 1024];
__device__ __nv_bfloat16 g_blo_b[128 * 1024];
__device__ __nv_bfloat16 g_bhi_1[128 * 128];
__device__ __nv_bfloat16 g_blo_1[128 * 128];
__device__ __nv_bfloat16 g_bhi_2[128 * 128];
__device__ __nv_bfloat16 g_blo_2[128 * 128];
__device__ __nv_bfloat16 g_bhi_3[64 * 128];
__device__ __nv_bfloat16 g_blo_3[64 * 128];

// ---------------- CSR construction ----------------------------------------
__global__ void zero_cnt_kernel(int n) {
    int i = blockIdx.x * blockDim.x + threadIdx.x;
    if (i < n) g_cnt[i] = 0;
}

__global__ void count_kernel(const int* __restrict__ dst, int E) {
    int i = blockIdx.x * blockDim.x + threadIdx.x;
    if (i < E) atomicAdd(&g_cnt[dst[i]], 1);
}

__global__ void dinv_kernel(int n) {
    int i = blockIdx.x * blockDim.x + threadIdx.x;
    if (i < n) g_dinv[i] = rsqrtf((float)(g_cnt[i] + 1));  // +1 self loop
}

// multi-block scan: per-block exclusive scan + block sums
__global__ void scan_block_kernel(int n) {
    __shared__ int sh[1024];
    int tid = threadIdx.x;
    int i = blockIdx.x * 1024 + tid;
    int v = (i < n) ? g_cnt[i] : 0;
    sh[tid] = v;
    __syncthreads();
    for (int off = 1; off < 1024; off <<= 1) {
        int t = (tid >= off) ? sh[tid - off] : 0;
        __syncthreads();
        sh[tid] += t;
        __syncthreads();
    }
    if (i < n) g_rowtmp[i] = sh[tid] - v;   // exclusive within block
    if (tid == 1023) g_bsum[blockIdx.x] = sh[1023];
}

__global__ void scan_bsum_kernel(int nb, int n) {
    __shared__ int sh[128];
    int tid = threadIdx.x;
    int v = (tid < nb) ? g_bsum[tid] : 0;
    sh[tid] = v;
    __syncthreads();
    for (int off = 1; off < 128; off <<= 1) {
        int t = (tid >= off) ? sh[tid - off] : 0;
        __syncthreads();
        sh[tid] += t;
        __syncthreads();
    }
    if (tid < nb) g_boff[tid] = sh[tid] - v;
    if (tid == 127) g_rowoff[n] = sh[127];
}

__global__ void scan_add_kernel(int n) {
    int i = blockIdx.x * blockDim.x + threadIdx.x;
    if (i >= n) return;
    int val = g_rowtmp[i] + g_boff[i >> 10];
    g_rowoff[i] = val;
    g_cursor[i] = val;
}

__global__ void fill_kernel(const int* __restrict__ src, const int* __restrict__ dst, int E) {
    int i = blockIdx.x * blockDim.x + threadIdx.x;
    if (i >= E) return;
    int s = src[i], d = dst[i];
    int p = atomicAdd(&g_cursor[d], 1);
    g_esrc[p]  = s;
    g_enorm[p] = g_dinv[s] * g_dinv[d];
}

// -------- weight convert: W[K][NC] fp32 -> B-format [n][k] bf16 hi/lo -------
__global__ void convw_kernel(const float* __restrict__ W,
                             __nv_bfloat16* __restrict__ bhi,
                             __nv_bfloat16* __restrict__ blo, int K, int NC) {
    int idx = blockIdx.x * blockDim.x + threadIdx.x;
    if (idx >= K * NC) return;
    int k = idx / NC, n = idx % NC;
    float v = W[idx];
    __nv_bfloat16 h = __float2bfloat16(v);
    float r = v - __bfloat162float(h);
    bhi[n * K + k] = h;
    blo[n * K + k] = __float2bfloat16(r);
}

// ---------------- HMMA (mma.sync) split-bf16 GEMM ---------------------------
// C[nrows, NCOL] = A[nrows, KTOT] @ W via bf16 hi/lo (3 passes), fp32 acc.
// CTA: 128 x NCOL tile, 256 threads (8 warps: 4 in M x 2 in N), BK = 32.
// Double-buffered smem: A prefetched to regs (fp32, converted post-compute),
// B copied via cp.async (bf16, no conversion).
__device__ __forceinline__ void mma16816(float* c, const uint32_t* a, const uint32_t* b) {
    asm volatile(
        "mma.sync.aligned.m16n8k16.row.col.f32.bf16.bf16.f32 "
        "{%0,%1,%2,%3}, {%4,%5,%6,%7}, {%8,%9}, {%0,%1,%2,%3};\n"
        : "+f"(c[0]), "+f"(c[1]), "+f"(c[2]), "+f"(c[3])
        : "r"(a[0]), "r"(a[1]), "r"(a[2]), "r"(a[3]), "r"(b[0]), "r"(b[1]));
}

__device__ __forceinline__ void split_f4(float4 v, uint2& hi, uint2& lo) {
    __nv_bfloat16 hx = __float2bfloat16(v.x), hy = __float2bfloat16(v.y);
    __nv_bfloat16 hz = __float2bfloat16(v.z), hw = __float2bfloat16(v.w);
    float rx = v.x - __bfloat162float(hx), ry = v.y - __bfloat162float(hy);
    float rz = v.z - __bfloat162float(hz), rw = v.w - __bfloat162float(hw);
    uint32_t hxu = __bfloat16_as_ushort(hx), hyu = __bfloat16_as_ushort(hy);
    uint32_t hzu = __bfloat16_as_ushort(hz), hwu = __bfloat16_as_ushort(hw);
    uint32_t lxu = __bfloat16_as_ushort(__float2bfloat16(rx));
    uint32_t lyu = __bfloat16_as_ushort(__float2bfloat16(ry));
    uint32_t lzu = __bfloat16_as_ushort(__float2bfloat16(rz));
    uint32_t lwu = __bfloat16_as_ushort(__float2bfloat16(rw));
    hi = make_uint2(hxu | (hyu << 16), hzu | (hwu << 16));
    lo = make_uint2(lxu | (lyu << 16), lzu | (lwu << 16));
}

__device__ __forceinline__ void cp_async16(uint32_t saddr, const void* g) {
    asm volatile("cp.async.cg.shared.global [%0], [%1], 16;" :: "r"(saddr), "l"(g));
}
#define CP_COMMIT() asm volatile("cp.async.commit_group;" ::: "memory")
#define CP_WAIT0()  asm volatile("cp.async.wait_group 0;" ::: "memory")

template <int NCOL>
__global__ void __launch_bounds__(256, 2) gemm_mma_kernel(
    const float* __restrict__ A,
    const __nv_bfloat16* __restrict__ Bhi0, const __nv_bfloat16* __restrict__ Blo0,
    const __nv_bfloat16* __restrict__ Bhi1, const __nv_bfloat16* __restrict__ Blo1,
    const float* __restrict__ bias0, const float* __restrict__ bias1,
    float* __restrict__ C, int nrows, int KTOT, int userRows)
{
    constexpr int STR = 40;               // smem row stride in halves (bank-safe)
    constexpr int WN  = NCOL / 2;         // per-warp N extent (64 or 32)
    constexpr int NF  = WN / 8;           // n-fragments per warp (8 or 4)
    constexpr int ASZ = 128 * STR;        // halves per A buffer
    constexpr int BSZ = NCOL * STR;       // halves per B buffer

    extern __shared__ uint16_t sm[];
    uint16_t* As_hi = sm;                 // [2][ASZ]
    uint16_t* As_lo = sm + 2 * ASZ;       // [2][ASZ]
    uint16_t* Bs_hi = sm + 4 * ASZ;       // [2][BSZ]
    uint16_t* Bs_lo = sm + 4 * ASZ + 2 * BSZ;

    const int tid  = threadIdx.x;
    const int wid  = tid >> 5;
    const int lane = tid & 31;
    const int wm   = wid & 3;             // warp m index (0..3) -> rows wm*32
    const int wn   = wid >> 2;            // warp n index (0..1) -> cols wn*WN
    const int g    = lane >> 2;           // 0..7
    const int t    = lane & 3;            // 0..3

    const int r0   = blockIdx.x * 128;
    const bool set0 = (r0 < userRows);
    const __nv_bfloat16* Bhi = set0 ? Bhi0 : Bhi1;
    const __nv_bfloat16* Blo = set0 ? Blo0 : Blo1;
    const float* bias = set0 ? bias0 : bias1;

    float acc[2][NF][4];
#pragma unroll
    for (int mf = 0; mf < 2; mf++)
#pragma unroll
        for (int nf = 0; nf < NF; nf++)
#pragma unroll
            for (int i = 0; i < 4; i++) acc[mf][nf][i] = 0.f;

    // per-thread load indices
    const int arow[4] = { (tid + 0*256) >> 3, (tid + 1*256) >> 3,
                          (tid + 2*256) >> 3, (tid + 3*256) >> 3 };
    const int ac4 = (tid & 7) << 2;       // same for all 4 (tid+i*256 keeps low 3 bits)

    float4 areg[4];

    const int nchunk = KTOT >> 5;         // BK = 32

    // ---- helpers as lambdas ----
    auto loadA = [&](int c) {
        const int k0 = c << 5;
#pragma unroll
        for (int i = 0; i < 4; i++) {
            int row = arow[i];
            if (r0 + row < nrows)
                areg[i] = *(const float4*)(A + (size_t)(r0 + row) * KTOT + k0 + ac4);
            else
                areg[i] = make_float4(0.f, 0.f, 0.f, 0.f);
        }
    };
    auto storeA = [&](int buf) {
        uint16_t* ah_s = As_hi + buf * ASZ;
        uint16_t* al_s = As_lo + buf * ASZ;
#pragma unroll
        for (int i = 0; i < 4; i++) {
            uint2 hi, lo;
            split_f4(areg[i], hi, lo);
            *(uint2*)&ah_s[arow[i] * STR + ac4] = hi;
            *(uint2*)&al_s[arow[i] * STR + ac4] = lo;
        }
    };
    auto cpB = [&](int c, int buf) {
        const int k0 = c << 5;
        uint16_t* bh_s = Bs_hi + buf * BSZ;
        uint16_t* bl_s = Bs_lo + buf * BSZ;
#pragma unroll
        for (int i = 0; i < NCOL / 64; i++) {
            int idx = tid + i * 256;          // < NCOL*4
            int n  = idx >> 2;
            int c8 = (idx & 3) << 3;          // 0,8,16,24
            uint32_t sh = (uint32_t)__cvta_generic_to_shared(&bh_s[n * STR + c8]);
            uint32_t sl = (uint32_t)__cvta_generic_to_shared(&bl_s[n * STR + c8]);
            cp_async16(sh, Bhi + (size_t)n * KTOT + k0 + c8);
            cp_async16(sl, Blo + (size_t)n * KTOT + k0 + c8);
        }
        CP_COMMIT();
    };
    auto compute = [&](int buf) {
        uint16_t* ah_s = As_hi + buf * ASZ;
        uint16_t* al_s = As_lo + buf * ASZ;
        uint16_t* bh_s = Bs_hi + buf * BSZ;
        uint16_t* bl_s = Bs_lo + buf * BSZ;
#pragma unroll
        for (int ks = 0; ks < 2; ks++) {
            uint32_t ah[2][4], al[2][4];
#pragma unroll
            for (int mf = 0; mf < 2; mf++) {
                int rb = (wm * 32 + mf * 16 + g) * STR + ks * 16 + t * 2;
                int r8 = rb + 8 * STR;
                ah[mf][0] = *(const uint32_t*)&ah_s[rb];
                ah[mf][1] = *(const uint32_t*)&ah_s[r8];
                ah[mf][2] = *(const uint32_t*)&ah_s[rb + 8];
                ah[mf][3] = *(const uint32_t*)&ah_s[r8 + 8];
                al[mf][0] = *(const uint32_t*)&al_s[rb];
                al[mf][1] = *(const uint32_t*)&al_s[r8];
                al[mf][2] = *(const uint32_t*)&al_s[rb + 8];
                al[mf][3] = *(const uint32_t*)&al_s[r8 + 8];
            }
#pragma unroll
            for (int nf = 0; nf < NF; nf++) {
                int bb = (wn * WN + nf * 8 + g) * STR + ks * 16 + t * 2;
                uint32_t bh[2], bl[2];
                bh[0] = *(const uint32_t*)&bh_s[bb];
                bh[1] = *(const uint32_t*)&bh_s[bb + 8];
                bl[0] = *(const uint32_t*)&bl_s[bb];
                bl[1] = *(const uint32_t*)&bl_s[bb + 8];
#pragma unroll
                for (int mf = 0; mf < 2; mf++) {
                    mma16816(acc[mf][nf], ah[mf], bh);
                    mma16816(acc[mf][nf], ah[mf], bl);
                    mma16816(acc[mf][nf], al[mf], bh);
                }
            }
        }
    };

    // ---- prolog: fill buffer 0 ----
    loadA(0);
    cpB(0, 0);
    storeA(0);
    CP_WAIT0();
    __syncthreads();

    // ---- main loop ----
    for (int c = 0; c < nchunk; c++) {
        const int cur = c & 1, nxt = cur ^ 1;
        const bool more = (c + 1 < nchunk);
        if (more) {
            loadA(c + 1);        // global -> regs (latency hidden by compute)
            cpB(c + 1, nxt);     // global -> smem async
        }
        compute(cur);
        __syncthreads();
        if (more) {
            storeA(nxt);
            CP_WAIT0();
            __syncthreads();
        }
    }

    // ---- epilogue: acc -> C (+bias) ----
#pragma unroll
    for (int mf = 0; mf < 2; mf++) {
        int row = r0 + wm * 32 + mf * 16 + g;
#pragma unroll
        for (int nf = 0; nf < NF; nf++) {
            int col = wn * WN + nf * 8 + t * 2;
            float bx = bias ? bias[col] : 0.f;
            float by = bias ? bias[col + 1] : 0.f;
            if (row < nrows) {
                float2 v;
                v.x = acc[mf][nf][0] + bx;
                v.y = acc[mf][nf][1] + by;
                *(float2*)(C + (size_t)row * NCOL + col) = v;
            }
            if (row + 8 < nrows) {
                float2 v;
                v.x = acc[mf][nf][2] + bx;
                v.y = acc[mf][nf][3] + by;
                *(float2*)(C + (size_t)(row + 8) * NCOL + col) = v;
            }
        }
    }
}

// ---------------- CSR aggregation -------------------------------------------
template <int HD, bool RELU>
__global__ void aggregate_kernel(const float* __restrict__ hw,
                                 const float* __restrict__ bias,
                                 float* __restrict__ out, int n)
{
    constexpr int V = HD / 32;    // 4 or 2
    int gw = (blockIdx.x * blockDim.x + threadIdx.x) >> 5;
    if (gw >= n) return;
    int lane = threadIdx.x & 31;

    float acc[V];
    float di = g_dinv[gw];
    float sl = di * di;

    if (V == 4) {
        float4 r = *(const float4*)(hw + (size_t)gw * HD + lane * 4);
        acc[0] = r.x * sl; acc[1] = r.y * sl; acc[2] = r.z * sl; acc[3] = r.w * sl;
    } else {
        float2 r = *(const float2*)(hw + (size_t)gw * HD + lane * 2);
        acc[0] = r.x * sl; acc[1] = r.y * sl;
    }

    int e   = g_rowoff[gw];
    int end = g_rowoff[gw + 1];
    for (; e < end; e++) {
        int   s  = __ldg(&g_esrc[e]);
        float nm = __ldg(&g_enorm[e]);
        if (V == 4) {
            float4 r = *(const float4*)(hw + (size_t)s * HD + lane * 4);
            acc[0] += r.x * nm; acc[1] += r.y * nm;
            acc[2] += r.z * nm; acc[3] += r.w * nm;
        } else {
            float2 r = *(const float2*)(hw + (size_t)s * HD + lane * 2);
            acc[0] += r.x * nm; acc[1] += r.y * nm;
        }
    }

#pragma unroll
    for (int v = 0; v < V; v++) {
        float val = acc[v] + bias[lane * V + v];
        if (RELU) val = fmaxf(val, 0.f);
        acc[v] = val;
    }
    if (V == 4) {
        float4 o; o.x = acc[0]; o.y = acc[1]; o.z = acc[2]; o.w = acc[3];
        *(float4*)(out + (size_t)gw * HD + lane * 4) = o;
    } else {
        float2 o; o.x = acc[0]; o.y = acc[1];
        *(float2*)(out + (size_t)gw * HD + lane * 2) = o;
    }
}

// ---------------- launch ----------------------------------------------------
extern "C" void kernel_launch(void* const* d_in, const int* in_sizes, int n_in,
                              void* d_out, int out_size)
{
    const float* x  = (const float*)d_in[0];
    const int*   ei = (const int*)  d_in[1];
    const float* Wu = (const float*)d_in[2];
    const float* bu = (const float*)d_in[3];
    const float* Wb = (const float*)d_in[4];
    const float* bb = (const float*)d_in[5];
    const float* W1 = (const float*)d_in[6];
    const float* b1 = (const float*)d_in[7];
    const float* W2 = (const float*)d_in[8];
    const float* b2 = (const float*)d_in[9];
    const float* W3 = (const float*)d_in[10];
    const float* b3 = (const float*)d_in[11];

    const int N = in_sizes[0] / FEAT;     // 101024
    const int E = in_sizes[1] / 2;        // 2000000
    const int userRows = 1024;

    float *h_ptr, *hw_ptr;
    cudaGetSymbolAddress((void**)&h_ptr,  g_h);
    cudaGetSymbolAddress((void**)&hw_ptr, g_hw);

    __nv_bfloat16 *bhi_u, *blo_u, *bhi_b, *blo_b, *bhi_1, *blo_1, *bhi_2, *blo_2, *bhi_3, *blo_3;
    cudaGetSymbolAddress((void**)&bhi_u, g_bhi_u);
    cudaGetSymbolAddress((void**)&blo_u, g_blo_u);
    cudaGetSymbolAddress((void**)&bhi_b, g_bhi_b);
    cudaGetSymbolAddress((void**)&blo_b, g_blo_b);
    cudaGetSymbolAddress((void**)&bhi_1, g_bhi_1);
    cudaGetSymbolAddress((void**)&blo_1, g_blo_1);
    cudaGetSymbolAddress((void**)&bhi_2, g_bhi_2);
    cudaGetSymbolAddress((void**)&blo_2, g_blo_2);
    cudaGetSymbolAddress((void**)&bhi_3, g_bhi_3);
    cudaGetSymbolAddress((void**)&blo_3, g_blo_3);

    const int* src = ei;
    const int* dst = ei + E;

    // dynamic smem opt-in (double-buffered tiles)
    constexpr int SMEM128 = (4 * 128 * 40 + 4 * 128 * 40) * 2;  // 81920 B
    constexpr int SMEM64  = (4 * 128 * 40 + 4 * 64  * 40) * 2;  // 61440 B
    cudaFuncSetAttribute(gemm_mma_kernel<128>, cudaFuncAttributeMaxDynamicSharedMemorySize, SMEM128);
    cudaFuncSetAttribute(gemm_mma_kernel<64>,  cudaFuncAttributeMaxDynamicSharedMemorySize, SMEM64);

    // one-time side-stream/event setup (host resources; identical work per call)
    static cudaStream_t s2 = 0;
    static cudaEvent_t evFork = 0, evJoin = 0;
    static int sinit = 0;
    if (!sinit) {
        sinit = 1;
        if (cudaStreamCreateWithFlags(&s2, cudaStreamNonBlocking) != cudaSuccess) s2 = 0;
        if (s2) {
            if (cudaEventCreateWithFlags(&evFork, cudaEventDisableTiming) != cudaSuccess ||
                cudaEventCreateWithFlags(&evJoin, cudaEventDisableTiming) != cudaSuccess)
                s2 = 0;
        }
    }
    const bool fork = (s2 != 0);
    cudaStream_t sc = fork ? s2 : 0;      // CSR-chain stream

    if (fork) {
        cudaEventRecord(evFork, 0);
        cudaStreamWaitEvent(s2, evFork, 0);
    }

    // 1) degree / CSR build (side stream — overlaps with convw + GEMMs)
    zero_cnt_kernel<<<(N + 255) / 256, 256, 0, sc>>>(N);
    count_kernel<<<(E + 255) / 256, 256, 0, sc>>>(dst, E);
    dinv_kernel<<<(N + 255) / 256, 256, 0, sc>>>(N);
    int nb = (N + 1023) / 1024;
    scan_block_kernel<<<nb, 1024, 0, sc>>>(N);
    scan_bsum_kernel<<<1, 128, 0, sc>>>(nb, N);
    scan_add_kernel<<<(N + 255) / 256, 256, 0, sc>>>(N);
    fill_kernel<<<(E + 255) / 256, 256, 0, sc>>>(src, dst, E);
    if (fork) cudaEventRecord(evJoin, s2);

    // 2) weight conversion (fp32 -> transposed bf16 hi/lo) — main stream
    convw_kernel<<<(FEAT * 128 + 255) / 256, 256>>>(Wu, bhi_u, blo_u, FEAT, 128);
    convw_kernel<<<(FEAT * 128 + 255) / 256, 256>>>(Wb, bhi_b, blo_b, FEAT, 128);
    convw_kernel<<<(128 * 128 + 255) / 256, 256>>>(W1, bhi_1, blo_1, 128, 128);
    convw_kernel<<<(128 * 128 + 255) / 256, 256>>>(W2, bhi_2, blo_2, 128, 128);
    convw_kernel<<<(128 * 64  + 255) / 256, 256>>>(W3, bhi_3, blo_3, 128, 64);

    int gemmBlocks = (N + 127) / 128;
    int aggBlocks  = (N + 7) / 8;         // 8 warps / block

    // 3) projection: h = x @ (Wu|Wb) + (bu|bb)
    gemm_mma_kernel<128><<<gemmBlocks, 256, SMEM128>>>(
        x, bhi_u, blo_u, bhi_b, blo_b, bu, bb, h_ptr, N, FEAT, userRows);

    // 4) layer 1: hw = h @ W1 ; h = relu(agg(hw) + b1)
    gemm_mma_kernel<128><<<gemmBlocks, 256, SMEM128>>>(
        h_ptr, bhi_1, blo_1, bhi_1, blo_1, nullptr, nullptr, hw_ptr, N, H0, 0x7fffffff);

    if (fork) cudaStreamWaitEvent(0, evJoin, 0);   // CSR ready before aggregation
    aggregate_kernel<128, true><<<aggBlocks, 256>>>(hw_ptr, b1, h_ptr, N);

    // 5) layer 2
    gemm_mma_kernel<128><<<gemmBlocks, 256, SMEM128>>>(
        h_ptr, bhi_2, blo_2, bhi_2, blo_2, nullptr, nullptr, hw_ptr, N, H0, 0x7fffffff);
    aggregate_kernel<128, true><<<aggBlocks, 256>>>(hw_ptr, b2, h_ptr, N);

    // 6) layer 3 (out dim 64, no relu) -> d_out
    gemm_mma_kernel<64><<<gemmBlocks, 256, SMEM64>>>(
        h_ptr, bhi_3, blo_3, bhi_3, blo_3, nullptr, nullptr, hw_ptr, N, H0, 0x7fffffff);
    aggregate_kernel<64, false><<<aggBlocks, 256>>>(hw_ptr, b3, (float*)d_out, N);
}

// round 8
// speedup vs baseline: 2.1281x; 1.0121x over previous
#include <cuda_runtime.h>
#include <cuda_bf16.h>
#include <cuda_fp16.h>
#include <cstdint>

// Problem constants (fixed by the dataset)
#define MAXN 101024
#define MAXE 2000000
#define FEAT 1024
#define H0 128

// ---------------- scratch (device globals; no allocation allowed) ----------
__device__ float  g_h [(size_t)MAXN * H0];   // node features (ping)
__device__ float  g_hw[(size_t)MAXN * H0];   // h @ W       (pong, fp32)
__device__ __half g_hw16[(size_t)MAXN * H0]; // h @ W       (fp16 gather table)
__device__ float g_dinv[MAXN];
__device__ int   g_cnt[MAXN];
__device__ int   g_rowoff[MAXN + 1];
__device__ int   g_cursor[MAXN];
__device__ int   g_rowtmp[MAXN];
__device__ int   g_bsum[128];
__device__ int   g_boff[128];
__device__ int   g_esrc[MAXE];
__device__ float g_enorm[MAXE];

// bf16 hi/lo weight buffers, transposed to B-format [n][k]
__device__ __nv_bfloat16 g_bhi_u[128 * 1024];
__device__ __nv_bfloat16 g_blo_u[128 * 1024];
__device__ __nv_bfloat16 g_bhi_b[128 * 1024];
__device__ __nv_bfloat16 g_blo_b[128 * 1024];
__device__ __nv_bfloat16 g_bhi_1[128 * 128];
__device__ __nv_bfloat16 g_blo_1[128 * 128];
__device__ __nv_bfloat16 g_bhi_2[128 * 128];
__device__ __nv_bfloat16 g_blo_2[128 * 128];
__device__ __nv_bfloat16 g_bhi_3[64 * 128];
__device__ __nv_bfloat16 g_blo_3[64 * 128];

// ---------------- CSR construction ----------------------------------------
__global__ void zero_cnt_kernel(int n) {
    int i = blockIdx.x * blockDim.x + threadIdx.x;
    if (i < n) g_cnt[i] = 0;
}

__global__ void count_kernel(const int* __restrict__ dst, int E) {
    int i = blockIdx.x * blockDim.x + threadIdx.x;
    if (i < E) atomicAdd(&g_cnt[dst[i]], 1);
}

__global__ void dinv_kernel(int n) {
    int i = blockIdx.x * blockDim.x + threadIdx.x;
    if (i < n) g_dinv[i] = rsqrtf((float)(g_cnt[i] + 1));  // +1 self loop
}

// multi-block scan: per-block exclusive scan + block sums
__global__ void scan_block_kernel(int n) {
    __shared__ int sh[1024];
    int tid = threadIdx.x;
    int i = blockIdx.x * 1024 + tid;
    int v = (i < n) ? g_cnt[i] : 0;
    sh[tid] = v;
    __syncthreads();
    for (int off = 1; off < 1024; off <<= 1) {
        int t = (tid >= off) ? sh[tid - off] : 0;
        __syncthreads();
        sh[tid] += t;
        __syncthreads();
    }
    if (i < n) g_rowtmp[i] = sh[tid] - v;   // exclusive within block
    if (tid == 1023) g_bsum[blockIdx.x] = sh[1023];
}

__global__ void scan_bsum_kernel(int nb, int n) {
    __shared__ int sh[128];
    int tid = threadIdx.x;
    int v = (tid < nb) ? g_bsum[tid] : 0;
    sh[tid] = v;
    __syncthreads();
    for (int off = 1; off < 128; off <<= 1) {
        int t = (tid >= off) ? sh[tid - off] : 0;
        __syncthreads();
        sh[tid] += t;
        __syncthreads();
    }
    if (tid < nb) g_boff[tid] = sh[tid] - v;
    if (tid == 127) g_rowoff[n] = sh[127];
}

__global__ void scan_add_kernel(int n) {
    int i = blockIdx.x * blockDim.x + threadIdx.x;
    if (i >= n) return;
    int val = g_rowtmp[i] + g_boff[i >> 10];
    g_rowoff[i] = val;
    g_cursor[i] = val;
}

__global__ void fill_kernel(const int* __restrict__ src, const int* __restrict__ dst, int E) {
    int i = blockIdx.x * blockDim.x + threadIdx.x;
    if (i >= E) return;
    int s = src[i], d = dst[i];
    int p = atomicAdd(&g_cursor[d], 1);
    g_esrc[p]  = s;
    g_enorm[p] = g_dinv[s] * g_dinv[d];
}

// -------- weight convert: W[K][NC] fp32 -> B-format [n][k] bf16 hi/lo -------
__global__ void convw_kernel(const float* __restrict__ W,
                             __nv_bfloat16* __restrict__ bhi,
                             __nv_bfloat16* __restrict__ blo, int K, int NC) {
    int idx = blockIdx.x * blockDim.x + threadIdx.x;
    if (idx >= K * NC) return;
    int k = idx / NC, n = idx % NC;
    float v = W[idx];
    __nv_bfloat16 h = __float2bfloat16(v);
    float r = v - __bfloat162float(h);
    bhi[n * K + k] = h;
    blo[n * K + k] = __float2bfloat16(r);
}

// ---------------- HMMA (mma.sync) split-bf16 GEMM ---------------------------
// C[nrows, NCOL] = A[nrows, KTOT] @ W via bf16 hi/lo (3 passes), fp32 acc.
// CTA: 128 x NCOL tile, 256 threads (8 warps: 4 in M x 2 in N), BK = 32.
// Double-buffered smem; optional fp16 secondary output (gather table).
__device__ __forceinline__ void mma16816(float* c, const uint32_t* a, const uint32_t* b) {
    asm volatile(
        "mma.sync.aligned.m16n8k16.row.col.f32.bf16.bf16.f32 "
        "{%0,%1,%2,%3}, {%4,%5,%6,%7}, {%8,%9}, {%0,%1,%2,%3};\n"
        : "+f"(c[0]), "+f"(c[1]), "+f"(c[2]), "+f"(c[3])
        : "r"(a[0]), "r"(a[1]), "r"(a[2]), "r"(a[3]), "r"(b[0]), "r"(b[1]));
}

__device__ __forceinline__ void split_f4(float4 v, uint2& hi, uint2& lo) {
    __nv_bfloat16 hx = __float2bfloat16(v.x), hy = __float2bfloat16(v.y);
    __nv_bfloat16 hz = __float2bfloat16(v.z), hw = __float2bfloat16(v.w);
    float rx = v.x - __bfloat162float(hx), ry = v.y - __bfloat162float(hy);
    float rz = v.z - __bfloat162float(hz), rw = v.w - __bfloat162float(hw);
    uint32_t hxu = __bfloat16_as_ushort(hx), hyu = __bfloat16_as_ushort(hy);
    uint32_t hzu = __bfloat16_as_ushort(hz), hwu = __bfloat16_as_ushort(hw);
    uint32_t lxu = __bfloat16_as_ushort(__float2bfloat16(rx));
    uint32_t lyu = __bfloat16_as_ushort(__float2bfloat16(ry));
    uint32_t lzu = __bfloat16_as_ushort(__float2bfloat16(rz));
    uint32_t lwu = __bfloat16_as_ushort(__float2bfloat16(rw));
    hi = make_uint2(hxu | (hyu << 16), hzu | (hwu << 16));
    lo = make_uint2(lxu | (lyu << 16), lzu | (lwu << 16));
}

__device__ __forceinline__ void cp_async16(uint32_t saddr, const void* g) {
    asm volatile("cp.async.cg.shared.global [%0], [%1], 16;" :: "r"(saddr), "l"(g));
}
#define CP_COMMIT() asm volatile("cp.async.commit_group;" ::: "memory")
#define CP_WAIT0()  asm volatile("cp.async.wait_group 0;" ::: "memory")

template <int NCOL>
__global__ void __launch_bounds__(256, 2) gemm_mma_kernel(
    const float* __restrict__ A,
    const __nv_bfloat16* __restrict__ Bhi0, const __nv_bfloat16* __restrict__ Blo0,
    const __nv_bfloat16* __restrict__ Bhi1, const __nv_bfloat16* __restrict__ Blo1,
    const float* __restrict__ bias0, const float* __restrict__ bias1,
    float* __restrict__ C, __half* __restrict__ C16,
    int nrows, int KTOT, int userRows)
{
    constexpr int STR = 40;               // smem row stride in halves (bank-safe)
    constexpr int WN  = NCOL / 2;         // per-warp N extent (64 or 32)
    constexpr int NF  = WN / 8;           // n-fragments per warp (8 or 4)
    constexpr int ASZ = 128 * STR;        // halves per A buffer
    constexpr int BSZ = NCOL * STR;       // halves per B buffer

    extern __shared__ uint16_t sm[];
    uint16_t* As_hi = sm;                 // [2][ASZ]
    uint16_t* As_lo = sm + 2 * ASZ;       // [2][ASZ]
    uint16_t* Bs_hi = sm + 4 * ASZ;       // [2][BSZ]
    uint16_t* Bs_lo = sm + 4 * ASZ + 2 * BSZ;

    const int tid  = threadIdx.x;
    const int wid  = tid >> 5;
    const int lane = tid & 31;
    const int wm   = wid & 3;             // warp m index (0..3) -> rows wm*32
    const int wn   = wid >> 2;            // warp n index (0..1) -> cols wn*WN
    const int g    = lane >> 2;           // 0..7
    const int t    = lane & 3;            // 0..3

    const int r0   = blockIdx.x * 128;
    const bool set0 = (r0 < userRows);
    const __nv_bfloat16* Bhi = set0 ? Bhi0 : Bhi1;
    const __nv_bfloat16* Blo = set0 ? Blo0 : Blo1;
    const float* bias = set0 ? bias0 : bias1;

    float acc[2][NF][4];
#pragma unroll
    for (int mf = 0; mf < 2; mf++)
#pragma unroll
        for (int nf = 0; nf < NF; nf++)
#pragma unroll
            for (int i = 0; i < 4; i++) acc[mf][nf][i] = 0.f;

    // per-thread load indices
    const int arow[4] = { (tid + 0*256) >> 3, (tid + 1*256) >> 3,
                          (tid + 2*256) >> 3, (tid + 3*256) >> 3 };
    const int ac4 = (tid & 7) << 2;       // same for all 4 (tid+i*256 keeps low 3 bits)

    float4 areg[4];

    const int nchunk = KTOT >> 5;         // BK = 32

    // ---- helpers as lambdas ----
    auto loadA = [&](int c) {
        const int k0 = c << 5;
#pragma unroll
        for (int i = 0; i < 4; i++) {
            int row = arow[i];
            if (r0 + row < nrows)
                areg[i] = *(const float4*)(A + (size_t)(r0 + row) * KTOT + k0 + ac4);
            else
                areg[i] = make_float4(0.f, 0.f, 0.f, 0.f);
        }
    };
    auto storeA = [&](int buf) {
        uint16_t* ah_s = As_hi + buf * ASZ;
        uint16_t* al_s = As_lo + buf * ASZ;
#pragma unroll
        for (int i = 0; i < 4; i++) {
            uint2 hi, lo;
            split_f4(areg[i], hi, lo);
            *(uint2*)&ah_s[arow[i] * STR + ac4] = hi;
            *(uint2*)&al_s[arow[i] * STR + ac4] = lo;
        }
    };
    auto cpB = [&](int c, int buf) {
        const int k0 = c << 5;
        uint16_t* bh_s = Bs_hi + buf * BSZ;
        uint16_t* bl_s = Bs_lo + buf * BSZ;
#pragma unroll
        for (int i = 0; i < NCOL / 64; i++) {
            int idx = tid + i * 256;          // < NCOL*4
            int n  = idx >> 2;
            int c8 = (idx & 3) << 3;          // 0,8,16,24
            uint32_t sh = (uint32_t)__cvta_generic_to_shared(&bh_s[n * STR + c8]);
            uint32_t sl = (uint32_t)__cvta_generic_to_shared(&bl_s[n * STR + c8]);
            cp_async16(sh, Bhi + (size_t)n * KTOT + k0 + c8);
            cp_async16(sl, Blo + (size_t)n * KTOT + k0 + c8);
        }
        CP_COMMIT();
    };
    auto compute = [&](int buf) {
        uint16_t* ah_s = As_hi + buf * ASZ;
        uint16_t* al_s = As_lo + buf * ASZ;
        uint16_t* bh_s = Bs_hi + buf * BSZ;
        uint16_t* bl_s = Bs_lo + buf * BSZ;
#pragma unroll
        for (int ks = 0; ks < 2; ks++) {
            uint32_t ah[2][4], al[2][4];
#pragma unroll
            for (int mf = 0; mf < 2; mf++) {
                int rb = (wm * 32 + mf * 16 + g) * STR + ks * 16 + t * 2;
                int r8 = rb + 8 * STR;
                ah[mf][0] = *(const uint32_t*)&ah_s[rb];
                ah[mf][1] = *(const uint32_t*)&ah_s[r8];
                ah[mf][2] = *(const uint32_t*)&ah_s[rb + 8];
                ah[mf][3] = *(const uint32_t*)&ah_s[r8 + 8];
                al[mf][0] = *(const uint32_t*)&al_s[rb];
                al[mf][1] = *(const uint32_t*)&al_s[r8];
                al[mf][2] = *(const uint32_t*)&al_s[rb + 8];
                al[mf][3] = *(const uint32_t*)&al_s[r8 + 8];
            }
#pragma unroll
            for (int nf = 0; nf < NF; nf++) {
                int bb = (wn * WN + nf * 8 + g) * STR + ks * 16 + t * 2;
                uint32_t bh[2], bl[2];
                bh[0] = *(const uint32_t*)&bh_s[bb];
                bh[1] = *(const uint32_t*)&bh_s[bb + 8];
                bl[0] = *(const uint32_t*)&bl_s[bb];
                bl[1] = *(const uint32_t*)&bl_s[bb + 8];
#pragma unroll
                for (int mf = 0; mf < 2; mf++) {
                    mma16816(acc[mf][nf], ah[mf], bh);
                    mma16816(acc[mf][nf], ah[mf], bl);
                    mma16816(acc[mf][nf], al[mf], bh);
                }
            }
        }
    };

    // ---- prolog: fill buffer 0 ----
    loadA(0);
    cpB(0, 0);
    storeA(0);
    CP_WAIT0();
    __syncthreads();

    // ---- main loop ----
    for (int c = 0; c < nchunk; c++) {
        const int cur = c & 1, nxt = cur ^ 1;
        const bool more = (c + 1 < nchunk);
        if (more) {
            loadA(c + 1);        // global -> regs (latency hidden by compute)
            cpB(c + 1, nxt);     // global -> smem async
        }
        compute(cur);
        __syncthreads();
        if (more) {
            storeA(nxt);
            CP_WAIT0();
            __syncthreads();
        }
    }

    // ---- epilogue: acc -> C (+bias), optional fp16 copy ----
#pragma unroll
    for (int mf = 0; mf < 2; mf++) {
        int row = r0 + wm * 32 + mf * 16 + g;
#pragma unroll
        for (int nf = 0; nf < NF; nf++) {
            int col = wn * WN + nf * 8 + t * 2;
            float bx = bias ? bias[col] : 0.f;
            float by = bias ? bias[col + 1] : 0.f;
            if (row < nrows) {
                float2 v;
                v.x = acc[mf][nf][0] + bx;
                v.y = acc[mf][nf][1] + by;
                *(float2*)(C + (size_t)row * NCOL + col) = v;
                if (C16)
                    *(__half2*)(C16 + (size_t)row * NCOL + col) = __float22half2_rn(v);
            }
            if (row + 8 < nrows) {
                float2 v;
                v.x = acc[mf][nf][2] + bx;
                v.y = acc[mf][nf][3] + by;
                *(float2*)(C + (size_t)(row + 8) * NCOL + col) = v;
                if (C16)
                    *(__half2*)(C16 + (size_t)(row + 8) * NCOL + col) = __float22half2_rn(v);
            }
        }
    }
}

// ---------------- CSR aggregation -------------------------------------------
// self term from fp32 hw; neighbor gathers from fp16 hw16 (half the bytes)
template <int HD, bool RELU>
__global__ void aggregate_kernel(const float* __restrict__ hw,
                                 const __half* __restrict__ hw16,
                                 const float* __restrict__ bias,
                                 float* __restrict__ out, int n)
{
    constexpr int V = HD / 32;    // 4 or 2
    int gw = (blockIdx.x * blockDim.x + threadIdx.x) >> 5;
    if (gw >= n) return;
    int lane = threadIdx.x & 31;

    float acc[V];
    float di = g_dinv[gw];
    float sl = di * di;

    if (V == 4) {
        float4 r = *(const float4*)(hw + (size_t)gw * HD + lane * 4);
        acc[0] = r.x * sl; acc[1] = r.y * sl; acc[2] = r.z * sl; acc[3] = r.w * sl;
    } else {
        float2 r = *(const float2*)(hw + (size_t)gw * HD + lane * 2);
        acc[0] = r.x * sl; acc[1] = r.y * sl;
    }

    int e   = g_rowoff[gw];
    int end = g_rowoff[gw + 1];
    for (; e < end; e++) {
        int   s  = __ldg(&g_esrc[e]);
        float nm = __ldg(&g_enorm[e]);
        if (V == 4) {
            int2 raw = *(const int2*)(hw16 + (size_t)s * HD + lane * 4);
            float2 f0 = __half22float2(*(__half2*)&raw.x);
            float2 f1 = __half22float2(*(__half2*)&raw.y);
            acc[0] += f0.x * nm; acc[1] += f0.y * nm;
            acc[2] += f1.x * nm; acc[3] += f1.y * nm;
        } else {
            int raw = *(const int*)(hw16 + (size_t)s * HD + lane * 2);
            float2 f0 = __half22float2(*(__half2*)&raw);
            acc[0] += f0.x * nm; acc[1] += f0.y * nm;
        }
    }

#pragma unroll
    for (int v = 0; v < V; v++) {
        float val = acc[v] + bias[lane * V + v];
        if (RELU) val = fmaxf(val, 0.f);
        acc[v] = val;
    }
    if (V == 4) {
        float4 o; o.x = acc[0]; o.y = acc[1]; o.z = acc[2]; o.w = acc[3];
        *(float4*)(out + (size_t)gw * HD + lane * 4) = o;
    } else {
        float2 o; o.x = acc[0]; o.y = acc[1];
        *(float2*)(out + (size_t)gw * HD + lane * 2) = o;
    }
}

// ---------------- launch ----------------------------------------------------
extern "C" void kernel_launch(void* const* d_in, const int* in_sizes, int n_in,
                              void* d_out, int out_size)
{
    const float* x  = (const float*)d_in[0];
    const int*   ei = (const int*)  d_in[1];
    const float* Wu = (const float*)d_in[2];
    const float* bu = (const float*)d_in[3];
    const float* Wb = (const float*)d_in[4];
    const float* bb = (const float*)d_in[5];
    const float* W1 = (const float*)d_in[6];
    const float* b1 = (const float*)d_in[7];
    const float* W2 = (const float*)d_in[8];
    const float* b2 = (const float*)d_in[9];
    const float* W3 = (const float*)d_in[10];
    const float* b3 = (const float*)d_in[11];

    const int N = in_sizes[0] / FEAT;     // 101024
    const int E = in_sizes[1] / 2;        // 2000000
    const int userRows = 1024;

    float *h_ptr, *hw_ptr;
    __half *hw16_ptr;
    cudaGetSymbolAddress((void**)&h_ptr,   g_h);
    cudaGetSymbolAddress((void**)&hw_ptr,  g_hw);
    cudaGetSymbolAddress((void**)&hw16_ptr, g_hw16);

    __nv_bfloat16 *bhi_u, *blo_u, *bhi_b, *blo_b, *bhi_1, *blo_1, *bhi_2, *blo_2, *bhi_3, *blo_3;
    cudaGetSymbolAddress((void**)&bhi_u, g_bhi_u);
    cudaGetSymbolAddress((void**)&blo_u, g_blo_u);
    cudaGetSymbolAddress((void**)&bhi_b, g_bhi_b);
    cudaGetSymbolAddress((void**)&blo_b, g_blo_b);
    cudaGetSymbolAddress((void**)&bhi_1, g_bhi_1);
    cudaGetSymbolAddress((void**)&blo_1, g_blo_1);
    cudaGetSymbolAddress((void**)&bhi_2, g_bhi_2);
    cudaGetSymbolAddress((void**)&blo_2, g_blo_2);
    cudaGetSymbolAddress((void**)&bhi_3, g_bhi_3);
    cudaGetSymbolAddress((void**)&blo_3, g_blo_3);

    const int* src = ei;
    const int* dst = ei + E;

    // dynamic smem opt-in (double-buffered tiles)
    constexpr int SMEM128 = (4 * 128 * 40 + 4 * 128 * 40) * 2;  // 81920 B
    constexpr int SMEM64  = (4 * 128 * 40 + 4 * 64  * 40) * 2;  // 61440 B
    cudaFuncSetAttribute(gemm_mma_kernel<128>, cudaFuncAttributeMaxDynamicSharedMemorySize, SMEM128);
    cudaFuncSetAttribute(gemm_mma_kernel<64>,  cudaFuncAttributeMaxDynamicSharedMemorySize, SMEM64);

    // one-time side-stream/event setup (host resources; identical work per call)
    static cudaStream_t s2 = 0;
    static cudaEvent_t evFork = 0, evJoin = 0;
    static int sinit = 0;
    if (!sinit) {
        sinit = 1;
        if (cudaStreamCreateWithFlags(&s2, cudaStreamNonBlocking) != cudaSuccess) s2 = 0;
        if (s2) {
            if (cudaEventCreateWithFlags(&evFork, cudaEventDisableTiming) != cudaSuccess ||
                cudaEventCreateWithFlags(&evJoin, cudaEventDisableTiming) != cudaSuccess)
                s2 = 0;
        }
    }
    const bool fork = (s2 != 0);
    cudaStream_t sc = fork ? s2 : 0;      // CSR-chain stream

    if (fork) {
        cudaEventRecord(evFork, 0);
        cudaStreamWaitEvent(s2, evFork, 0);
    }

    // 1) degree / CSR build (side stream — overlaps with convw + GEMMs)
    zero_cnt_kernel<<<(N + 255) / 256, 256, 0, sc>>>(N);
    count_kernel<<<(E + 255) / 256, 256, 0, sc>>>(dst, E);
    dinv_kernel<<<(N + 255) / 256, 256, 0, sc>>>(N);
    int nb = (N + 1023) / 1024;
    scan_block_kernel<<<nb, 1024, 0, sc>>>(N);
    scan_bsum_kernel<<<1, 128, 0, sc>>>(nb, N);
    scan_add_kernel<<<(N + 255) / 256, 256, 0, sc>>>(N);
    fill_kernel<<<(E + 255) / 256, 256, 0, sc>>>(src, dst, E);
    if (fork) cudaEventRecord(evJoin, s2);

    // 2) weight conversion (fp32 -> transposed bf16 hi/lo) — main stream
    convw_kernel<<<(FEAT * 128 + 255) / 256, 256>>>(Wu, bhi_u, blo_u, FEAT, 128);
    convw_kernel<<<(FEAT * 128 + 255) / 256, 256>>>(Wb, bhi_b, blo_b, FEAT, 128);
    convw_kernel<<<(128 * 128 + 255) / 256, 256>>>(W1, bhi_1, blo_1, 128, 128);
    convw_kernel<<<(128 * 128 + 255) / 256, 256>>>(W2, bhi_2, blo_2, 128, 128);
    convw_kernel<<<(128 * 64  + 255) / 256, 256>>>(W3, bhi_3, blo_3, 128, 64);

    int gemmBlocks = (N + 127) / 128;
    int aggBlocks  = (N + 7) / 8;         // 8 warps / block

    // 3) projection: h = x @ (Wu|Wb) + (bu|bb)   (no fp16 copy needed)
    gemm_mma_kernel<128><<<gemmBlocks, 256, SMEM128>>>(
        x, bhi_u, blo_u, bhi_b, blo_b, bu, bb, h_ptr, nullptr, N, FEAT, userRows);

    // 4) layer 1: hw = h @ W1 ; h = relu(agg(hw) + b1)
    gemm_mma_kernel<128><<<gemmBlocks, 256, SMEM128>>>(
        h_ptr, bhi_1, blo_1, bhi_1, blo_1, nullptr, nullptr, hw_ptr, hw16_ptr, N, H0, 0x7fffffff);

    if (fork) cudaStreamWaitEvent(0, evJoin, 0);   // CSR ready before aggregation
    aggregate_kernel<128, true><<<aggBlocks, 256>>>(hw_ptr, hw16_ptr, b1, h_ptr, N);

    // 5) layer 2
    gemm_mma_kernel<128><<<gemmBlocks, 256, SMEM128>>>(
        h_ptr, bhi_2, blo_2, bhi_2, blo_2, nullptr, nullptr, hw_ptr, hw16_ptr, N, H0, 0x7fffffff);
    aggregate_kernel<128, true><<<aggBlocks, 256>>>(hw_ptr, hw16_ptr, b2, h_ptr, N);

    // 6) layer 3 (out dim 64, no relu) -> d_out
    gemm_mma_kernel<64><<<gemmBlocks, 256, SMEM64>>>(
        h_ptr, bhi_3, blo_3, bhi_3, blo_3, nullptr, nullptr, hw_ptr, hw16_ptr, N, H0, 0x7fffffff);
    aggregate_kernel<64, false><<<aggBlocks, 256>>>(hw_ptr, hw16_ptr, b3, (float*)d_out, N);
}

// round 12
// speedup vs baseline: 2.7052x; 1.2712x over previous
#include <cuda_runtime.h>
#include <cuda_bf16.h>
#include <cuda_fp16.h>
#include <cstdint>

// Problem constants (fixed by the dataset)
#define MAXN 101024
#define MAXE 2000000
#define FEAT 1024
#define H0 128

// ---------------- scratch (device globals; no allocation allowed) ----------
__device__ float  g_h [(size_t)MAXN * H0];   // node features (ping)
__device__ float  g_hw[(size_t)MAXN * H0];   // h @ W       (pong, fp32)
__device__ __half g_hw16[(size_t)MAXN * H0]; // h @ W       (fp16 gather table)
__device__ float g_dinv[MAXN];
__device__ int   g_cnt[MAXN];
__device__ int   g_rowoff[MAXN + 1];
__device__ int   g_cursor[MAXN];
__device__ int   g_rowtmp[MAXN];
__device__ int   g_bsum[128];
__device__ int   g_boff[128];
__device__ int   g_esrc[MAXE];
__device__ float g_enorm[MAXE];

// fp16 weight buffers, transposed to B-format [n][k]
__device__ __half g_bh_u[128 * 1024];
__device__ __half g_bh_b[128 * 1024];
__device__ __half g_bh_1[128 * 128];
__device__ __half g_bh_2[128 * 128];
__device__ __half g_bh_3[64 * 128];

// ---------------- CSR construction ----------------------------------------
__global__ void zero_cnt_kernel(int n) {
    int i = blockIdx.x * blockDim.x + threadIdx.x;
    if (i < n) g_cnt[i] = 0;
}

__global__ void count_kernel(const int* __restrict__ dst, int E) {
    int i = blockIdx.x * blockDim.x + threadIdx.x;
    if (i < E) atomicAdd(&g_cnt[dst[i]], 1);
}

__global__ void dinv_kernel(int n) {
    int i = blockIdx.x * blockDim.x + threadIdx.x;
    if (i < n) g_dinv[i] = rsqrtf((float)(g_cnt[i] + 1));  // +1 self loop
}

// multi-block scan: per-block exclusive scan + block sums
__global__ void scan_block_kernel(int n) {
    __shared__ int sh[1024];
    int tid = threadIdx.x;
    int i = blockIdx.x * 1024 + tid;
    int v = (i < n) ? g_cnt[i] : 0;
    sh[tid] = v;
    __syncthreads();
    for (int off = 1; off < 1024; off <<= 1) {
        int t = (tid >= off) ? sh[tid - off] : 0;
        __syncthreads();
        sh[tid] += t;
        __syncthreads();
    }
    if (i < n) g_rowtmp[i] = sh[tid] - v;   // exclusive within block
    if (tid == 1023) g_bsum[blockIdx.x] = sh[1023];
}

__global__ void scan_bsum_kernel(int nb, int n) {
    __shared__ int sh[128];
    int tid = threadIdx.x;
    int v = (tid < nb) ? g_bsum[tid] : 0;
    sh[tid] = v;
    __syncthreads();
    for (int off = 1; off < 128; off <<= 1) {
        int t = (tid >= off) ? sh[tid - off] : 0;
        __syncthreads();
        sh[tid] += t;
        __syncthreads();
    }
    if (tid < nb) g_boff[tid] = sh[tid] - v;
    if (tid == 127) g_rowoff[n] = sh[127];
}

__global__ void scan_add_kernel(int n) {
    int i = blockIdx.x * blockDim.x + threadIdx.x;
    if (i >= n) return;
    int val = g_rowtmp[i] + g_boff[i >> 10];
    g_rowoff[i] = val;
    g_cursor[i] = val;
}

__global__ void fill_kernel(const int* __restrict__ src, const int* __restrict__ dst, int E) {
    int i = blockIdx.x * blockDim.x + threadIdx.x;
    if (i >= E) return;
    int s = src[i], d = dst[i];
    int p = atomicAdd(&g_cursor[d], 1);
    g_esrc[p]  = s;
    g_enorm[p] = g_dinv[s] * g_dinv[d];
}

// -------- weight convert: W[K][NC] fp32 -> B-format [n][k] fp16 -------------
__global__ void convw_kernel(const float* __restrict__ W,
                             __half* __restrict__ bh, int K, int NC) {
    int idx = blockIdx.x * blockDim.x + threadIdx.x;
    if (idx >= K * NC) return;
    int k = idx / NC, n = idx % NC;
    bh[n * K + k] = __float2half_rn(W[idx]);
}

// ---------------- HMMA (mma.sync) split-fp16 GEMM ---------------------------
// C[nrows, NCOL] = A[nrows, KTOT] @ W, A split to fp16 hi+lo (2 passes),
// W single fp16, fp32 accumulate. CTA: 128 x NCOL, 256 threads, BK = 32.
__device__ __forceinline__ void mma16816(float* c, const uint32_t* a, const uint32_t* b) {
    asm volatile(
        "mma.sync.aligned.m16n8k16.row.col.f32.f16.f16.f32 "
        "{%0,%1,%2,%3}, {%4,%5,%6,%7}, {%8,%9}, {%0,%1,%2,%3};\n"
        : "+f"(c[0]), "+f"(c[1]), "+f"(c[2]), "+f"(c[3])
        : "r"(a[0]), "r"(a[1]), "r"(a[2]), "r"(a[3]), "r"(b[0]), "r"(b[1]));
}

__device__ __forceinline__ void split_f4_h(float4 v, uint2& hi, uint2& lo) {
    __half2 h0 = __floats2half2_rn(v.x, v.y);
    __half2 h1 = __floats2half2_rn(v.z, v.w);
    float2 f0 = __half22float2(h0);
    float2 f1 = __half22float2(h1);
    __half2 l0 = __floats2half2_rn(v.x - f0.x, v.y - f0.y);
    __half2 l1 = __floats2half2_rn(v.z - f1.x, v.w - f1.y);
    hi = make_uint2(*(uint32_t*)&h0, *(uint32_t*)&h1);
    lo = make_uint2(*(uint32_t*)&l0, *(uint32_t*)&l1);
}

__device__ __forceinline__ void cp_async16(uint32_t saddr, const void* g) {
    asm volatile("cp.async.cg.shared.global [%0], [%1], 16;" :: "r"(saddr), "l"(g));
}
#define CP_COMMIT() asm volatile("cp.async.commit_group;" ::: "memory")
#define CP_WAIT0()  asm volatile("cp.async.wait_group 0;" ::: "memory")

template <int NCOL>
__global__ void __launch_bounds__(256, 2) gemm_mma_kernel(
    const float* __restrict__ A,
    const __half* __restrict__ Bh0, const __half* __restrict__ Bh1,
    const float* __restrict__ bias0, const float* __restrict__ bias1,
    float* __restrict__ C, __half* __restrict__ C16,
    int nrows, int KTOT, int userRows)
{
    constexpr int STR = 40;               // smem row stride in halves (bank-safe)
    constexpr int WN  = NCOL / 2;         // per-warp N extent (64 or 32)
    constexpr int NF  = WN / 8;           // n-fragments per warp (8 or 4)
    constexpr int ASZ = 128 * STR;        // halves per A buffer
    constexpr int BSZ = NCOL * STR;       // halves per B buffer

    extern __shared__ uint16_t sm[];
    uint16_t* As_hi = sm;                 // [2][ASZ]
    uint16_t* As_lo = sm + 2 * ASZ;       // [2][ASZ]
    uint16_t* Bs    = sm + 4 * ASZ;       // [2][BSZ]

    const int tid  = threadIdx.x;
    const int wid  = tid >> 5;
    const int lane = tid & 31;
    const int wm   = wid & 3;             // warp m index (0..3) -> rows wm*32
    const int wn   = wid >> 2;            // warp n index (0..1) -> cols wn*WN
    const int g    = lane >> 2;           // 0..7
    const int t    = lane & 3;            // 0..3

    const int r0   = blockIdx.x * 128;
    const bool set0 = (r0 < userRows);
    const __half* Bh = set0 ? Bh0 : Bh1;
    const float* bias = set0 ? bias0 : bias1;

    float acc[2][NF][4];
#pragma unroll
    for (int mf = 0; mf < 2; mf++)
#pragma unroll
        for (int nf = 0; nf < NF; nf++)
#pragma unroll
            for (int i = 0; i < 4; i++) acc[mf][nf][i] = 0.f;

    // per-thread load indices
    const int arow[4] = { (tid + 0*256) >> 3, (tid + 1*256) >> 3,
                          (tid + 2*256) >> 3, (tid + 3*256) >> 3 };
    const int ac4 = (tid & 7) << 2;       // same for all 4 (tid+i*256 keeps low 3 bits)

    float4 areg[4];

    const int nchunk = KTOT >> 5;         // BK = 32

    auto loadA = [&](int c) {
        const int k0 = c << 5;
#pragma unroll
        for (int i = 0; i < 4; i++) {
            int row = arow[i];
            if (r0 + row < nrows)
                areg[i] = *(const float4*)(A + (size_t)(r0 + row) * KTOT + k0 + ac4);
            else
                areg[i] = make_float4(0.f, 0.f, 0.f, 0.f);
        }
    };
    auto storeA = [&](int buf) {
        uint16_t* ah_s = As_hi + buf * ASZ;
        uint16_t* al_s = As_lo + buf * ASZ;
#pragma unroll
        for (int i = 0; i < 4; i++) {
            uint2 hi, lo;
            split_f4_h(areg[i], hi, lo);
            *(uint2*)&ah_s[arow[i] * STR + ac4] = hi;
            *(uint2*)&al_s[arow[i] * STR + ac4] = lo;
        }
    };
    auto cpB = [&](int c, int buf) {
        const int k0 = c << 5;
        uint16_t* b_s = Bs + buf * BSZ;
#pragma unroll
        for (int i = 0; i < NCOL / 64; i++) {
            int idx = tid + i * 256;          // < NCOL*4
            int n  = idx >> 2;
            int c8 = (idx & 3) << 3;          // 0,8,16,24
            uint32_t sh = (uint32_t)__cvta_generic_to_shared(&b_s[n * STR + c8]);
            cp_async16(sh, Bh + (size_t)n * KTOT + k0 + c8);
        }
        CP_COMMIT();
    };
    auto compute = [&](int buf) {
        uint16_t* ah_s = As_hi + buf * ASZ;
        uint16_t* al_s = As_lo + buf * ASZ;
        uint16_t* b_s  = Bs + buf * BSZ;
#pragma unroll
        for (int ks = 0; ks < 2; ks++) {
            uint32_t ah[2][4], al[2][4];
#pragma unroll
            for (int mf = 0; mf < 2; mf++) {
                int rb = (wm * 32 + mf * 16 + g) * STR + ks * 16 + t * 2;
                int r8 = rb + 8 * STR;
                ah[mf][0] = *(const uint32_t*)&ah_s[rb];
                ah[mf][1] = *(const uint32_t*)&ah_s[r8];
                ah[mf][2] = *(const uint32_t*)&ah_s[rb + 8];
                ah[mf][3] = *(const uint32_t*)&ah_s[r8 + 8];
                al[mf][0] = *(const uint32_t*)&al_s[rb];
                al[mf][1] = *(const uint32_t*)&al_s[r8];
                al[mf][2] = *(const uint32_t*)&al_s[rb + 8];
                al[mf][3] = *(const uint32_t*)&al_s[r8 + 8];
            }
#pragma unroll
            for (int nf = 0; nf < NF; nf++) {
                int bb = (wn * WN + nf * 8 + g) * STR + ks * 16 + t * 2;
                uint32_t bh[2];
                bh[0] = *(const uint32_t*)&b_s[bb];
                bh[1] = *(const uint32_t*)&b_s[bb + 8];
#pragma unroll
                for (int mf = 0; mf < 2; mf++) {
                    mma16816(acc[mf][nf], ah[mf], bh);
                    mma16816(acc[mf][nf], al[mf], bh);
                }
            }
        }
    };

    // ---- prolog: fill buffer 0 ----
    loadA(0);
    cpB(0, 0);
    storeA(0);
    CP_WAIT0();
    __syncthreads();

    // ---- main loop ----
    for (int c = 0; c < nchunk; c++) {
        const int cur = c & 1, nxt = cur ^ 1;
        const bool more = (c + 1 < nchunk);
        if (more) {
            loadA(c + 1);        // global -> regs (latency hidden by compute)
            cpB(c + 1, nxt);     // global -> smem async
        }
        compute(cur);
        __syncthreads();
        if (more) {
            storeA(nxt);
            CP_WAIT0();
            __syncthreads();
        }
    }

    // ---- epilogue: acc -> C (+bias), optional fp16 copy ----
#pragma unroll
    for (int mf = 0; mf < 2; mf++) {
        int row = r0 + wm * 32 + mf * 16 + g;
#pragma unroll
        for (int nf = 0; nf < NF; nf++) {
            int col = wn * WN + nf * 8 + t * 2;
            float bx = bias ? bias[col] : 0.f;
            float by = bias ? bias[col + 1] : 0.f;
            if (row < nrows) {
                float2 v;
                v.x = acc[mf][nf][0] + bx;
                v.y = acc[mf][nf][1] + by;
                *(float2*)(C + (size_t)row * NCOL + col) = v;
                if (C16)
                    *(__half2*)(C16 + (size_t)row * NCOL + col) = __float22half2_rn(v);
            }
            if (row + 8 < nrows) {
                float2 v;
                v.x = acc[mf][nf][2] + bx;
                v.y = acc[mf][nf][3] + by;
                *(float2*)(C + (size_t)(row + 8) * NCOL + col) = v;
                if (C16)
                    *(__half2*)(C16 + (size_t)(row + 8) * NCOL + col) = __float22half2_rn(v);
            }
        }
    }
}

// ---------------- CSR aggregation -------------------------------------------
// self term from fp32 hw; neighbor gathers from fp16 hw16, 4-way unrolled
// edge loop for MLP (gathers are independent across edges).
template <int HD, bool RELU>
__global__ void aggregate_kernel(const float* __restrict__ hw,
                                 const __half* __restrict__ hw16,
                                 const float* __restrict__ bias,
                                 float* __restrict__ out, int n)
{
    constexpr int V = HD / 32;    // 4 or 2
    int gw = (blockIdx.x * blockDim.x + threadIdx.x) >> 5;
    if (gw >= n) return;
    int lane = threadIdx.x & 31;

    float acc[V];
    float di = g_dinv[gw];
    float sl = di * di;

    if (V == 4) {
        float4 r = *(const float4*)(hw + (size_t)gw * HD + lane * 4);
        acc[0] = r.x * sl; acc[1] = r.y * sl; acc[2] = r.z * sl; acc[3] = r.w * sl;
    } else {
        float2 r = *(const float2*)(hw + (size_t)gw * HD + lane * 2);
        acc[0] = r.x * sl; acc[1] = r.y * sl;
    }

    int e   = g_rowoff[gw];
    int end = g_rowoff[gw + 1];

    // 4-way unrolled gather (independent loads -> MLP 4)
    for (; e + 4 <= end; e += 4) {
        int   s0 = __ldg(&g_esrc[e]),     s1 = __ldg(&g_esrc[e + 1]);
        int   s2 = __ldg(&g_esrc[e + 2]), s3 = __ldg(&g_esrc[e + 3]);
        float n0 = __ldg(&g_enorm[e]),     n1 = __ldg(&g_enorm[e + 1]);
        float n2 = __ldg(&g_enorm[e + 2]), n3 = __ldg(&g_enorm[e + 3]);
        if (V == 4) {
            int2 r0 = *(const int2*)(hw16 + (size_t)s0 * HD + lane * 4);
            int2 r1 = *(const int2*)(hw16 + (size_t)s1 * HD + lane * 4);
            int2 r2 = *(const int2*)(hw16 + (size_t)s2 * HD + lane * 4);
            int2 r3 = *(const int2*)(hw16 + (size_t)s3 * HD + lane * 4);
            float2 a0 = __half22float2(*(__half2*)&r0.x), b0 = __half22float2(*(__half2*)&r0.y);
            float2 a1 = __half22float2(*(__half2*)&r1.x), b1 = __half22float2(*(__half2*)&r1.y);
            float2 a2 = __half22float2(*(__half2*)&r2.x), b2 = __half22float2(*(__half2*)&r2.y);
            float2 a3 = __half22float2(*(__half2*)&r3.x), b3 = __half22float2(*(__half2*)&r3.y);
            acc[0] += a0.x * n0 + a1.x * n1 + a2.x * n2 + a3.x * n3;
            acc[1] += a0.y * n0 + a1.y * n1 + a2.y * n2 + a3.y * n3;
            acc[2] += b0.x * n0 + b1.x * n1 + b2.x * n2 + b3.x * n3;
            acc[3] += b0.y * n0 + b1.y * n1 + b2.y * n2 + b3.y * n3;
        } else {
            int r0 = *(const int*)(hw16 + (size_t)s0 * HD + lane * 2);
            int r1 = *(const int*)(hw16 + (size_t)s1 * HD + lane * 2);
            int r2 = *(const int*)(hw16 + (size_t)s2 * HD + lane * 2);
            int r3 = *(const int*)(hw16 + (size_t)s3 * HD + lane * 2);
            float2 a0 = __half22float2(*(__half2*)&r0);
            float2 a1 = __half22float2(*(__half2*)&r1);
            float2 a2 = __half22float2(*(__half2*)&r2);
            float2 a3 = __half22float2(*(__half2*)&r3);
            acc[0] += a0.x * n0 + a1.x * n1 + a2.x * n2 + a3.x * n3;
            acc[1] += a0.y * n0 + a1.y * n1 + a2.y * n2 + a3.y * n3;
        }
    }
    for (; e < end; e++) {
        int   s  = __ldg(&g_esrc[e]);
        float nm = __ldg(&g_enorm[e]);
        if (V == 4) {
            int2 raw = *(const int2*)(hw16 + (size_t)s * HD + lane * 4);
            float2 f0 = __half22float2(*(__half2*)&raw.x);
            float2 f1 = __half22float2(*(__half2*)&raw.y);
            acc[0] += f0.x * nm; acc[1] += f0.y * nm;
            acc[2] += f1.x * nm; acc[3] += f1.y * nm;
        } else {
            int raw = *(const int*)(hw16 + (size_t)s * HD + lane * 2);
            float2 f0 = __half22float2(*(__half2*)&raw);
            acc[0] += f0.x * nm; acc[1] += f0.y * nm;
        }
    }

#pragma unroll
    for (int v = 0; v < V; v++) {
        float val = acc[v] + bias[lane * V + v];
        if (RELU) val = fmaxf(val, 0.f);
        acc[v] = val;
    }
    if (V == 4) {
        float4 o; o.x = acc[0]; o.y = acc[1]; o.z = acc[2]; o.w = acc[3];
        *(float4*)(out + (size_t)gw * HD + lane * 4) = o;
    } else {
        float2 o; o.x = acc[0]; o.y = acc[1];
        *(float2*)(out + (size_t)gw * HD + lane * 2) = o;
    }
}

// ---------------- launch ----------------------------------------------------
extern "C" void kernel_launch(void* const* d_in, const int* in_sizes, int n_in,
                              void* d_out, int out_size)
{
    const float* x  = (const float*)d_in[0];
    const int*   ei = (const int*)  d_in[1];
    const float* Wu = (const float*)d_in[2];
    const float* bu = (const float*)d_in[3];
    const float* Wb = (const float*)d_in[4];
    const float* bb = (const float*)d_in[5];
    const float* W1 = (const float*)d_in[6];
    const float* b1 = (const float*)d_in[7];
    const float* W2 = (const float*)d_in[8];
    const float* b2 = (const float*)d_in[9];
    const float* W3 = (const float*)d_in[10];
    const float* b3 = (const float*)d_in[11];

    const int N = in_sizes[0] / FEAT;     // 101024
    const int E = in_sizes[1] / 2;        // 2000000
    const int userRows = 1024;

    float *h_ptr, *hw_ptr;
    __half *hw16_ptr;
    cudaGetSymbolAddress((void**)&h_ptr,    g_h);
    cudaGetSymbolAddress((void**)&hw_ptr,   g_hw);
    cudaGetSymbolAddress((void**)&hw16_ptr, g_hw16);

    __half *bh_u, *bh_b, *bh_1, *bh_2, *bh_3;
    cudaGetSymbolAddress((void**)&bh_u, g_bh_u);
    cudaGetSymbolAddress((void**)&bh_b, g_bh_b);
    cudaGetSymbolAddress((void**)&bh_1, g_bh_1);
    cudaGetSymbolAddress((void**)&bh_2, g_bh_2);
    cudaGetSymbolAddress((void**)&bh_3, g_bh_3);

    const int* src = ei;
    const int* dst = ei + E;

    // dynamic smem opt-in (double-buffered tiles)
    constexpr int SMEM128 = (4 * 128 * 40 + 2 * 128 * 40) * 2;  // 61440 B
    constexpr int SMEM64  = (4 * 128 * 40 + 2 * 64  * 40) * 2;  // 51200 B
    cudaFuncSetAttribute(gemm_mma_kernel<128>, cudaFuncAttributeMaxDynamicSharedMemorySize, SMEM128);
    cudaFuncSetAttribute(gemm_mma_kernel<64>,  cudaFuncAttributeMaxDynamicSharedMemorySize, SMEM64);

    // one-time side-stream/event setup (host resources; identical work per call)
    static cudaStream_t s2 = 0;
    static cudaEvent_t evFork = 0, evJoin = 0;
    static int sinit = 0;
    if (!sinit) {
        sinit = 1;
        if (cudaStreamCreateWithFlags(&s2, cudaStreamNonBlocking) != cudaSuccess) s2 = 0;
        if (s2) {
            if (cudaEventCreateWithFlags(&evFork, cudaEventDisableTiming) != cudaSuccess ||
                cudaEventCreateWithFlags(&evJoin, cudaEventDisableTiming) != cudaSuccess)
                s2 = 0;
        }
    }
    const bool fork = (s2 != 0);
    cudaStream_t sc = fork ? s2 : 0;      // CSR-chain stream

    if (fork) {
        cudaEventRecord(evFork, 0);
        cudaStreamWaitEvent(s2, evFork, 0);
    }

    // 1) degree / CSR build (side stream — overlaps with convw + GEMMs)
    zero_cnt_kernel<<<(N + 255) / 256, 256, 0, sc>>>(N);
    count_kernel<<<(E + 255) / 256, 256, 0, sc>>>(dst, E);
    dinv_kernel<<<(N + 255) / 256, 256, 0, sc>>>(N);
    int nb = (N + 1023) / 1024;
    scan_block_kernel<<<nb, 1024, 0, sc>>>(N);
    scan_bsum_kernel<<<1, 128, 0, sc>>>(nb, N);
    scan_add_kernel<<<(N + 255) / 256, 256, 0, sc>>>(N);
    fill_kernel<<<(E + 255) / 256, 256, 0, sc>>>(src, dst, E);
    if (fork) cudaEventRecord(evJoin, s2);

    // 2) weight conversion (fp32 -> transposed fp16) — main stream
    convw_kernel<<<(FEAT * 128 + 255) / 256, 256>>>(Wu, bh_u, FEAT, 128);
    convw_kernel<<<(FEAT * 128 + 255) / 256, 256>>>(Wb, bh_b, FEAT, 128);
    convw_kernel<<<(128 * 128 + 255) / 256, 256>>>(W1, bh_1, 128, 128);
    convw_kernel<<<(128 * 128 + 255) / 256, 256>>>(W2, bh_2, 128, 128);
    convw_kernel<<<(128 * 64  + 255) / 256, 256>>>(W3, bh_3, 128, 64);

    int gemmBlocks = (N + 127) / 128;
    int aggBlocks  = (N + 7) / 8;         // 8 warps / block

    // 3) projection: h = x @ (Wu|Wb) + (bu|bb)   (no fp16 copy needed)
    gemm_mma_kernel<128><<<gemmBlocks, 256, SMEM128>>>(
        x, bh_u, bh_b, bu, bb, h_ptr, nullptr, N, FEAT, userRows);

    // 4) layer 1: hw = h @ W1 ; h = relu(agg(hw) + b1)
    gemm_mma_kernel<128><<<gemmBlocks, 256, SMEM128>>>(
        h_ptr, bh_1, bh_1, nullptr, nullptr, hw_ptr, hw16_ptr, N, H0, 0x7fffffff);

    if (fork) cudaStreamWaitEvent(0, evJoin, 0);   // CSR ready before aggregation
    aggregate_kernel<128, true><<<aggBlocks, 256>>>(hw_ptr, hw16_ptr, b1, h_ptr, N);

    // 5) layer 2
    gemm_mma_kernel<128><<<gemmBlocks, 256, SMEM128>>>(
        h_ptr, bh_2, bh_2, nullptr, nullptr, hw_ptr, hw16_ptr, N, H0, 0x7fffffff);
    aggregate_kernel<128, true><<<aggBlocks, 256>>>(hw_ptr, hw16_ptr, b2, h_ptr, N);

    // 6) layer 3 (out dim 64, no relu) -> d_out
    gemm_mma_kernel<64><<<gemmBlocks, 256, SMEM64>>>(
        h_ptr, bh_3, bh_3, nullptr, nullptr, hw_ptr, hw16_ptr, N, H0, 0x7fffffff);
    aggregate_kernel<64, false><<<aggBlocks, 256>>>(hw_ptr, hw16_ptr, b3, (float*)d_out, N);
}

// round 14
// speedup vs baseline: 2.9623x; 1.0950x over previous
#include <cuda_runtime.h>
#include <cuda_bf16.h>
#include <cuda_fp16.h>
#include <cstdint>

// Problem constants (fixed by the dataset)
#define MAXN 101024
#define MAXE 2000000
#define FEAT 1024
#define H0 128

// ---------------- scratch (device globals; no allocation allowed) ----------
__device__ float  g_h [(size_t)MAXN * H0];   // node features (ping)
__device__ float  g_hw[(size_t)MAXN * H0];   // h @ W       (pong, fp32)
__device__ __half g_hw16[(size_t)MAXN * H0]; // h @ W       (fp16 gather table)
__device__ float g_dinv[MAXN];
__device__ int   g_cnt[MAXN];
__device__ int   g_rowoff[MAXN + 1];
__device__ int   g_cursor[MAXN];
__device__ int   g_rowtmp[MAXN];
__device__ int   g_bsum[128];
__device__ int   g_boff[128];
__device__ int   g_esrc[MAXE];
__device__ float g_enorm[MAXE];

// fp16 weight buffers, transposed to B-format [n][k]
__device__ __half g_bh_u[128 * 1024];
__device__ __half g_bh_b[128 * 1024];
__device__ __half g_bh_1[128 * 128];
__device__ __half g_bh_2[128 * 128];
__device__ __half g_bh_3[64 * 128];

// ---------------- CSR construction ----------------------------------------
__global__ void zero_cnt_kernel(int n) {
    int i = blockIdx.x * blockDim.x + threadIdx.x;
    if (i < n) g_cnt[i] = 0;
}

__global__ void count_kernel(const int* __restrict__ dst, int E) {
    int i = blockIdx.x * blockDim.x + threadIdx.x;
    if (i < E) atomicAdd(&g_cnt[dst[i]], 1);
}

__global__ void dinv_kernel(int n) {
    int i = blockIdx.x * blockDim.x + threadIdx.x;
    if (i < n) g_dinv[i] = rsqrtf((float)(g_cnt[i] + 1));  // +1 self loop
}

// multi-block scan: per-block exclusive scan + block sums
__global__ void scan_block_kernel(int n) {
    __shared__ int sh[1024];
    int tid = threadIdx.x;
    int i = blockIdx.x * 1024 + tid;
    int v = (i < n) ? g_cnt[i] : 0;
    sh[tid] = v;
    __syncthreads();
    for (int off = 1; off < 1024; off <<= 1) {
        int t = (tid >= off) ? sh[tid - off] : 0;
        __syncthreads();
        sh[tid] += t;
        __syncthreads();
    }
    if (i < n) g_rowtmp[i] = sh[tid] - v;   // exclusive within block
    if (tid == 1023) g_bsum[blockIdx.x] = sh[1023];
}

__global__ void scan_bsum_kernel(int nb, int n) {
    __shared__ int sh[128];
    int tid = threadIdx.x;
    int v = (tid < nb) ? g_bsum[tid] : 0;
    sh[tid] = v;
    __syncthreads();
    for (int off = 1; off < 128; off <<= 1) {
        int t = (tid >= off) ? sh[tid - off] : 0;
        __syncthreads();
        sh[tid] += t;
        __syncthreads();
    }
    if (tid < nb) g_boff[tid] = sh[tid] - v;
    if (tid == 127) g_rowoff[n] = sh[127];
}

__global__ void scan_add_kernel(int n) {
    int i = blockIdx.x * blockDim.x + threadIdx.x;
    if (i >= n) return;
    int val = g_rowtmp[i] + g_boff[i >> 10];
    g_rowoff[i] = val;
    g_cursor[i] = val;
}

__global__ void fill_kernel(const int* __restrict__ src, const int* __restrict__ dst, int E) {
    int i = blockIdx.x * blockDim.x + threadIdx.x;
    if (i >= E) return;
    int s = src[i], d = dst[i];
    int p = atomicAdd(&g_cursor[d], 1);
    g_esrc[p]  = s;
    g_enorm[p] = g_dinv[s] * g_dinv[d];
}

// -------- weight convert: W[K][NC] fp32 -> B-format [n][k] fp16 -------------
__global__ void convw_kernel(const float* __restrict__ W,
                             __half* __restrict__ bh, int K, int NC) {
    int idx = blockIdx.x * blockDim.x + threadIdx.x;
    if (idx >= K * NC) return;
    int k = idx / NC, n = idx % NC;
    bh[n * K + k] = __float2half_rn(W[idx]);
}

// ---------------- HMMA (mma.sync) fp16 GEMM ---------------------------------
// C[nrows, NCOL] = A[nrows, KTOT] @ W.  A fp32 -> fp16 hi(+lo if TWOPASS),
// W single fp16, fp32 accumulate. CTA: 128 x NCOL, 256 threads, BK = 32.
__device__ __forceinline__ void mma16816(float* c, const uint32_t* a, const uint32_t* b) {
    asm volatile(
        "mma.sync.aligned.m16n8k16.row.col.f32.f16.f16.f32 "
        "{%0,%1,%2,%3}, {%4,%5,%6,%7}, {%8,%9}, {%0,%1,%2,%3};\n"
        : "+f"(c[0]), "+f"(c[1]), "+f"(c[2]), "+f"(c[3])
        : "r"(a[0]), "r"(a[1]), "r"(a[2]), "r"(a[3]), "r"(b[0]), "r"(b[1]));
}

__device__ __forceinline__ void split_f4_h(float4 v, uint2& hi, uint2& lo) {
    __half2 h0 = __floats2half2_rn(v.x, v.y);
    __half2 h1 = __floats2half2_rn(v.z, v.w);
    float2 f0 = __half22float2(h0);
    float2 f1 = __half22float2(h1);
    __half2 l0 = __floats2half2_rn(v.x - f0.x, v.y - f0.y);
    __half2 l1 = __floats2half2_rn(v.z - f1.x, v.w - f1.y);
    hi = make_uint2(*(uint32_t*)&h0, *(uint32_t*)&h1);
    lo = make_uint2(*(uint32_t*)&l0, *(uint32_t*)&l1);
}
__device__ __forceinline__ void cvt_f4_h(float4 v, uint2& hi) {
    __half2 h0 = __floats2half2_rn(v.x, v.y);
    __half2 h1 = __floats2half2_rn(v.z, v.w);
    hi = make_uint2(*(uint32_t*)&h0, *(uint32_t*)&h1);
}

__device__ __forceinline__ void cp_async16(uint32_t saddr, const void* g) {
    asm volatile("cp.async.cg.shared.global [%0], [%1], 16;" :: "r"(saddr), "l"(g));
}
#define CP_COMMIT() asm volatile("cp.async.commit_group;" ::: "memory")
#define CP_WAIT0()  asm volatile("cp.async.wait_group 0;" ::: "memory")

template <int NCOL, bool TWOPASS>
__global__ void __launch_bounds__(256, 2) gemm_mma_kernel(
    const float* __restrict__ A,
    const __half* __restrict__ Bh0, const __half* __restrict__ Bh1,
    const float* __restrict__ bias0, const float* __restrict__ bias1,
    float* __restrict__ C, __half* __restrict__ C16,
    int nrows, int KTOT, int userRows)
{
    constexpr int STR = 40;               // smem row stride in halves (bank-safe)
    constexpr int WN  = NCOL / 2;         // per-warp N extent (64 or 32)
    constexpr int NF  = WN / 8;           // n-fragments per warp (8 or 4)
    constexpr int ASZ = 128 * STR;        // halves per A buffer
    constexpr int BSZ = NCOL * STR;       // halves per B buffer

    extern __shared__ uint16_t sm[];
    uint16_t* As_hi = sm;                 // [2][ASZ]
    uint16_t* As_lo = sm + 2 * ASZ;       // [2][ASZ] (unused if !TWOPASS)
    uint16_t* Bs    = sm + (TWOPASS ? 4 : 2) * ASZ;   // [2][BSZ]

    const int tid  = threadIdx.x;
    const int wid  = tid >> 5;
    const int lane = tid & 31;
    const int wm   = wid & 3;             // warp m index (0..3) -> rows wm*32
    const int wn   = wid >> 2;            // warp n index (0..1) -> cols wn*WN
    const int g    = lane >> 2;           // 0..7
    const int t    = lane & 3;            // 0..3

    const int r0   = blockIdx.x * 128;
    const bool set0 = (r0 < userRows);
    const __half* Bh = set0 ? Bh0 : Bh1;
    const float* bias = set0 ? bias0 : bias1;

    float acc[2][NF][4];
#pragma unroll
    for (int mf = 0; mf < 2; mf++)
#pragma unroll
        for (int nf = 0; nf < NF; nf++)
#pragma unroll
            for (int i = 0; i < 4; i++) acc[mf][nf][i] = 0.f;

    // per-thread load indices
    const int arow[4] = { (tid + 0*256) >> 3, (tid + 1*256) >> 3,
                          (tid + 2*256) >> 3, (tid + 3*256) >> 3 };
    const int ac4 = (tid & 7) << 2;       // same for all 4 (tid+i*256 keeps low 3 bits)

    float4 areg[4];

    const int nchunk = KTOT >> 5;         // BK = 32

    auto loadA = [&](int c) {
        const int k0 = c << 5;
#pragma unroll
        for (int i = 0; i < 4; i++) {
            int row = arow[i];
            if (r0 + row < nrows)
                areg[i] = *(const float4*)(A + (size_t)(r0 + row) * KTOT + k0 + ac4);
            else
                areg[i] = make_float4(0.f, 0.f, 0.f, 0.f);
        }
    };
    auto storeA = [&](int buf) {
        uint16_t* ah_s = As_hi + buf * ASZ;
        uint16_t* al_s = As_lo + buf * ASZ;
#pragma unroll
        for (int i = 0; i < 4; i++) {
            if (TWOPASS) {
                uint2 hi, lo;
                split_f4_h(areg[i], hi, lo);
                *(uint2*)&ah_s[arow[i] * STR + ac4] = hi;
                *(uint2*)&al_s[arow[i] * STR + ac4] = lo;
            } else {
                uint2 hi;
                cvt_f4_h(areg[i], hi);
                *(uint2*)&ah_s[arow[i] * STR + ac4] = hi;
            }
        }
    };
    auto cpB = [&](int c, int buf) {
        const int k0 = c << 5;
        uint16_t* b_s = Bs + buf * BSZ;
#pragma unroll
        for (int i = 0; i < NCOL / 64; i++) {
            int idx = tid + i * 256;          // < NCOL*4
            int n  = idx >> 2;
            int c8 = (idx & 3) << 3;          // 0,8,16,24
            uint32_t sh = (uint32_t)__cvta_generic_to_shared(&b_s[n * STR + c8]);
            cp_async16(sh, Bh + (size_t)n * KTOT + k0 + c8);
        }
        CP_COMMIT();
    };
    auto compute = [&](int buf) {
        uint16_t* ah_s = As_hi + buf * ASZ;
        uint16_t* al_s = As_lo + buf * ASZ;
        uint16_t* b_s  = Bs + buf * BSZ;
#pragma unroll
        for (int ks = 0; ks < 2; ks++) {
            uint32_t ah[2][4], al[2][4];
#pragma unroll
            for (int mf = 0; mf < 2; mf++) {
                int rb = (wm * 32 + mf * 16 + g) * STR + ks * 16 + t * 2;
                int r8 = rb + 8 * STR;
                ah[mf][0] = *(const uint32_t*)&ah_s[rb];
                ah[mf][1] = *(const uint32_t*)&ah_s[r8];
                ah[mf][2] = *(const uint32_t*)&ah_s[rb + 8];
                ah[mf][3] = *(const uint32_t*)&ah_s[r8 + 8];
                if (TWOPASS) {
                    al[mf][0] = *(const uint32_t*)&al_s[rb];
                    al[mf][1] = *(const uint32_t*)&al_s[r8];
                    al[mf][2] = *(const uint32_t*)&al_s[rb + 8];
                    al[mf][3] = *(const uint32_t*)&al_s[r8 + 8];
                }
            }
#pragma unroll
            for (int nf = 0; nf < NF; nf++) {
                int bb = (wn * WN + nf * 8 + g) * STR + ks * 16 + t * 2;
                uint32_t bh[2];
                bh[0] = *(const uint32_t*)&b_s[bb];
                bh[1] = *(const uint32_t*)&b_s[bb + 8];
#pragma unroll
                for (int mf = 0; mf < 2; mf++) {
                    mma16816(acc[mf][nf], ah[mf], bh);
                    if (TWOPASS) mma16816(acc[mf][nf], al[mf], bh);
                }
            }
        }
    };

    // ---- prolog: fill buffer 0 ----
    loadA(0);
    cpB(0, 0);
    storeA(0);
    CP_WAIT0();
    __syncthreads();

    // ---- main loop ----
    for (int c = 0; c < nchunk; c++) {
        const int cur = c & 1, nxt = cur ^ 1;
        const bool more = (c + 1 < nchunk);
        if (more) {
            loadA(c + 1);        // global -> regs (latency hidden by compute)
            cpB(c + 1, nxt);     // global -> smem async
        }
        compute(cur);
        __syncthreads();
        if (more) {
            storeA(nxt);
            CP_WAIT0();
            __syncthreads();
        }
    }

    // ---- epilogue: acc -> C (+bias), optional fp16 copy ----
#pragma unroll
    for (int mf = 0; mf < 2; mf++) {
        int row = r0 + wm * 32 + mf * 16 + g;
#pragma unroll
        for (int nf = 0; nf < NF; nf++) {
            int col = wn * WN + nf * 8 + t * 2;
            float bx = bias ? bias[col] : 0.f;
            float by = bias ? bias[col + 1] : 0.f;
            if (row < nrows) {
                float2 v;
                v.x = acc[mf][nf][0] + bx;
                v.y = acc[mf][nf][1] + by;
                *(float2*)(C + (size_t)row * NCOL + col) = v;
                if (C16)
                    *(__half2*)(C16 + (size_t)row * NCOL + col) = __float22half2_rn(v);
            }
            if (row + 8 < nrows) {
                float2 v;
                v.x = acc[mf][nf][2] + bx;
                v.y = acc[mf][nf][3] + by;
                *(float2*)(C + (size_t)(row + 8) * NCOL + col) = v;
                if (C16)
                    *(__half2*)(C16 + (size_t)(row + 8) * NCOL + col) = __float22half2_rn(v);
            }
        }
    }
}

// ---------------- CSR aggregation -------------------------------------------
// self term from fp32 hw; neighbor gathers from fp16 hw16, 8-way unrolled
// edge loop for MLP (gathers are independent across edges).
template <int HD, bool RELU>
__global__ void aggregate_kernel(const float* __restrict__ hw,
                                 const __half* __restrict__ hw16,
                                 const float* __restrict__ bias,
                                 float* __restrict__ out, int n)
{
    constexpr int V = HD / 32;    // 4 or 2
    int gw = (blockIdx.x * blockDim.x + threadIdx.x) >> 5;
    if (gw >= n) return;
    int lane = threadIdx.x & 31;

    float acc[V];
    float di = g_dinv[gw];
    float sl = di * di;

    if (V == 4) {
        float4 r = *(const float4*)(hw + (size_t)gw * HD + lane * 4);
        acc[0] = r.x * sl; acc[1] = r.y * sl; acc[2] = r.z * sl; acc[3] = r.w * sl;
    } else {
        float2 r = *(const float2*)(hw + (size_t)gw * HD + lane * 2);
        acc[0] = r.x * sl; acc[1] = r.y * sl;
    }

    int e   = g_rowoff[gw];
    int end = g_rowoff[gw + 1];

    // 8-way unrolled gather (independent loads -> MLP 8)
    for (; e + 8 <= end; e += 8) {
        int   s[8];
        float nm[8];
#pragma unroll
        for (int j = 0; j < 8; j++) {
            s[j]  = __ldg(&g_esrc[e + j]);
            nm[j] = __ldg(&g_enorm[e + j]);
        }
        if (V == 4) {
            int2 r[8];
#pragma unroll
            for (int j = 0; j < 8; j++)
                r[j] = *(const int2*)(hw16 + (size_t)s[j] * HD + lane * 4);
#pragma unroll
            for (int j = 0; j < 8; j++) {
                float2 a = __half22float2(*(__half2*)&r[j].x);
                float2 b = __half22float2(*(__half2*)&r[j].y);
                acc[0] += a.x * nm[j]; acc[1] += a.y * nm[j];
                acc[2] += b.x * nm[j]; acc[3] += b.y * nm[j];
            }
        } else {
            int r[8];
#pragma unroll
            for (int j = 0; j < 8; j++)
                r[j] = *(const int*)(hw16 + (size_t)s[j] * HD + lane * 2);
#pragma unroll
            for (int j = 0; j < 8; j++) {
                float2 a = __half22float2(*(__half2*)&r[j]);
                acc[0] += a.x * nm[j]; acc[1] += a.y * nm[j];
            }
        }
    }
    for (; e < end; e++) {
        int   s  = __ldg(&g_esrc[e]);
        float nm = __ldg(&g_enorm[e]);
        if (V == 4) {
            int2 raw = *(const int2*)(hw16 + (size_t)s * HD + lane * 4);
            float2 f0 = __half22float2(*(__half2*)&raw.x);
            float2 f1 = __half22float2(*(__half2*)&raw.y);
            acc[0] += f0.x * nm; acc[1] += f0.y * nm;
            acc[2] += f1.x * nm; acc[3] += f1.y * nm;
        } else {
            int raw = *(const int*)(hw16 + (size_t)s * HD + lane * 2);
            float2 f0 = __half22float2(*(__half2*)&raw);
            acc[0] += f0.x * nm; acc[1] += f0.y * nm;
        }
    }

#pragma unroll
    for (int v = 0; v < V; v++) {
        float val = acc[v] + bias[lane * V + v];
        if (RELU) val = fmaxf(val, 0.f);
        acc[v] = val;
    }
    if (V == 4) {
        float4 o; o.x = acc[0]; o.y = acc[1]; o.z = acc[2]; o.w = acc[3];
        *(float4*)(out + (size_t)gw * HD + lane * 4) = o;
    } else {
        float2 o; o.x = acc[0]; o.y = acc[1];
        *(float2*)(out + (size_t)gw * HD + lane * 2) = o;
    }
}

// ---------------- launch ----------------------------------------------------
extern "C" void kernel_launch(void* const* d_in, const int* in_sizes, int n_in,
                              void* d_out, int out_size)
{
    const float* x  = (const float*)d_in[0];
    const int*   ei = (const int*)  d_in[1];
    const float* Wu = (const float*)d_in[2];
    const float* bu = (const float*)d_in[3];
    const float* Wb = (const float*)d_in[4];
    const float* bb = (const float*)d_in[5];
    const float* W1 = (const float*)d_in[6];
    const float* b1 = (const float*)d_in[7];
    const float* W2 = (const float*)d_in[8];
    const float* b2 = (const float*)d_in[9];
    const float* W3 = (const float*)d_in[10];
    const float* b3 = (const float*)d_in[11];

    const int N = in_sizes[0] / FEAT;     // 101024
    const int E = in_sizes[1] / 2;        // 2000000
    const int userRows = 1024;

    float *h_ptr, *hw_ptr;
    __half *hw16_ptr;
    cudaGetSymbolAddress((void**)&h_ptr,    g_h);
    cudaGetSymbolAddress((void**)&hw_ptr,   g_hw);
    cudaGetSymbolAddress((void**)&hw16_ptr, g_hw16);

    __half *bh_u, *bh_b, *bh_1, *bh_2, *bh_3;
    cudaGetSymbolAddress((void**)&bh_u, g_bh_u);
    cudaGetSymbolAddress((void**)&bh_b, g_bh_b);
    cudaGetSymbolAddress((void**)&bh_1, g_bh_1);
    cudaGetSymbolAddress((void**)&bh_2, g_bh_2);
    cudaGetSymbolAddress((void**)&bh_3, g_bh_3);

    const int* src = ei;
    const int* dst = ei + E;

    // dynamic smem opt-in (double-buffered tiles)
    constexpr int SMEM_P  = (2 * 128 * 40 + 2 * 128 * 40) * 2;  // 1-pass proj: 40960 B
    constexpr int SMEM128 = (4 * 128 * 40 + 2 * 128 * 40) * 2;  // 61440 B
    constexpr int SMEM64  = (4 * 128 * 40 + 2 * 64  * 40) * 2;  // 51200 B
    cudaFuncSetAttribute((const void*)gemm_mma_kernel<128, false>, cudaFuncAttributeMaxDynamicSharedMemorySize, SMEM_P);
    cudaFuncSetAttribute((const void*)gemm_mma_kernel<128, true>,  cudaFuncAttributeMaxDynamicSharedMemorySize, SMEM128);
    cudaFuncSetAttribute((const void*)gemm_mma_kernel<64,  true>,  cudaFuncAttributeMaxDynamicSharedMemorySize, SMEM64);

    // one-time side-stream/event setup (host resources; identical work per call)
    static cudaStream_t s2 = 0;
    static cudaEvent_t evFork = 0, evJoin = 0;
    static int sinit = 0;
    if (!sinit) {
        sinit = 1;
        if (cudaStreamCreateWithFlags(&s2, cudaStreamNonBlocking) != cudaSuccess) s2 = 0;
        if (s2) {
            if (cudaEventCreateWithFlags(&evFork, cudaEventDisableTiming) != cudaSuccess ||
                cudaEventCreateWithFlags(&evJoin, cudaEventDisableTiming) != cudaSuccess)
                s2 = 0;
        }
    }
    const bool fork = (s2 != 0);
    cudaStream_t sc = fork ? s2 : 0;      // CSR-chain stream

    if (fork) {
        cudaEventRecord(evFork, 0);
        cudaStreamWaitEvent(s2, evFork, 0);
    }

    // 1) degree / CSR build (side stream — overlaps with convw + GEMMs)
    zero_cnt_kernel<<<(N + 255) / 256, 256, 0, sc>>>(N);
    count_kernel<<<(E + 255) / 256, 256, 0, sc>>>(dst, E);
    dinv_kernel<<<(N + 255) / 256, 256, 0, sc>>>(N);
    int nb = (N + 1023) / 1024;
    scan_block_kernel<<<nb, 1024, 0, sc>>>(N);
    scan_bsum_kernel<<<1, 128, 0, sc>>>(nb, N);
    scan_add_kernel<<<(N + 255) / 256, 256, 0, sc>>>(N);
    fill_kernel<<<(E + 255) / 256, 256, 0, sc>>>(src, dst, E);
    if (fork) cudaEventRecord(evJoin, s2);

    // 2) weight conversion (fp32 -> transposed fp16) — main stream
    convw_kernel<<<(FEAT * 128 + 255) / 256, 256>>>(Wu, bh_u, FEAT, 128);
    convw_kernel<<<(FEAT * 128 + 255) / 256, 256>>>(Wb, bh_b, FEAT, 128);
    convw_kernel<<<(128 * 128 + 255) / 256, 256>>>(W1, bh_1, 128, 128);
    convw_kernel<<<(128 * 128 + 255) / 256, 256>>>(W2, bh_2, 128, 128);
    convw_kernel<<<(128 * 64  + 255) / 256, 256>>>(W3, bh_3, 128, 64);

    int gemmBlocks = (N + 127) / 128;
    int aggBlocks  = (N + 7) / 8;         // 8 warps / block

    // 3) projection: h = x @ (Wu|Wb) + (bu|bb)   (single-pass fp16 A)
    gemm_mma_kernel<128, false><<<gemmBlocks, 256, SMEM_P>>>(
        x, bh_u, bh_b, bu, bb, h_ptr, nullptr, N, FEAT, userRows);

    // 4) layer 1: hw = h @ W1 ; h = relu(agg(hw) + b1)
    gemm_mma_kernel<128, true><<<gemmBlocks, 256, SMEM128>>>(
        h_ptr, bh_1, bh_1, nullptr, nullptr, hw_ptr, hw16_ptr, N, H0, 0x7fffffff);

    if (fork) cudaStreamWaitEvent(0, evJoin, 0);   // CSR ready before aggregation
    aggregate_kernel<128, true><<<aggBlocks, 256>>>(hw_ptr, hw16_ptr, b1, h_ptr, N);

    // 5) layer 2
    gemm_mma_kernel<128, true><<<gemmBlocks, 256, SMEM128>>>(
        h_ptr, bh_2, bh_2, nullptr, nullptr, hw_ptr, hw16_ptr, N, H0, 0x7fffffff);
    aggregate_kernel<128, true><<<aggBlocks, 256>>>(hw_ptr, hw16_ptr, b2, h_ptr, N);

    // 6) layer 3 (out dim 64, no relu) -> d_out
    gemm_mma_kernel<64, true><<<gemmBlocks, 256, SMEM64>>>(
        h_ptr, bh_3, bh_3, nullptr, nullptr, hw_ptr, hw16_ptr, N, H0, 0x7fffffff);
    aggregate_kernel<64, false><<<aggBlocks, 256>>>(hw_ptr, hw16_ptr, b3, (float*)d_out, N);
}

// round 15
// speedup vs baseline: 3.2232x; 1.0881x over previous
#include <cuda_runtime.h>
#include <cuda_bf16.h>
#include <cuda_fp16.h>
#include <cstdint>

// Problem constants (fixed by the dataset)
#define MAXN 101024
#define MAXE 2000000
#define FEAT 1024
#define H0 128

// ---------------- scratch (device globals; no allocation allowed) ----------
__device__ __half g_h16[(size_t)(MAXN + 128) * H0]; // node features, fp16 (padded tail)
__device__ float  g_hw[(size_t)MAXN * H0];   // h @ W (fp32, agg self-term)
__device__ __half g_hw16[(size_t)MAXN * H0]; // h @ W (fp16 gather table)
__device__ float g_dinv[MAXN];
__device__ int   g_cnt[MAXN];
__device__ int   g_rowoff[MAXN + 1];
__device__ int   g_cursor[MAXN];
__device__ int   g_rowtmp[MAXN];
__device__ int   g_bsum[128];
__device__ int   g_boff[128];
__device__ int   g_esrc[MAXE];
__device__ float g_enorm[MAXE];

// fp16 weight buffers, transposed to B-format [n][k]
__device__ __half g_bh_u[128 * 1024];
__device__ __half g_bh_b[128 * 1024];
__device__ __half g_bh_1[128 * 128];
__device__ __half g_bh_2[128 * 128];
__device__ __half g_bh_3[64 * 128];

// ---------------- CSR construction ----------------------------------------
__global__ void zero_cnt_kernel(int n) {
    int i = blockIdx.x * blockDim.x + threadIdx.x;
    if (i < n) g_cnt[i] = 0;
}

__global__ void count_kernel(const int* __restrict__ dst, int E) {
    int i = blockIdx.x * blockDim.x + threadIdx.x;
    if (i < E) atomicAdd(&g_cnt[dst[i]], 1);
}

__global__ void dinv_kernel(int n) {
    int i = blockIdx.x * blockDim.x + threadIdx.x;
    if (i < n) g_dinv[i] = rsqrtf((float)(g_cnt[i] + 1));  // +1 self loop
}

__global__ void scan_block_kernel(int n) {
    __shared__ int sh[1024];
    int tid = threadIdx.x;
    int i = blockIdx.x * 1024 + tid;
    int v = (i < n) ? g_cnt[i] : 0;
    sh[tid] = v;
    __syncthreads();
    for (int off = 1; off < 1024; off <<= 1) {
        int t = (tid >= off) ? sh[tid - off] : 0;
        __syncthreads();
        sh[tid] += t;
        __syncthreads();
    }
    if (i < n) g_rowtmp[i] = sh[tid] - v;
    if (tid == 1023) g_bsum[blockIdx.x] = sh[1023];
}

__global__ void scan_bsum_kernel(int nb, int n) {
    __shared__ int sh[128];
    int tid = threadIdx.x;
    int v = (tid < nb) ? g_bsum[tid] : 0;
    sh[tid] = v;
    __syncthreads();
    for (int off = 1; off < 128; off <<= 1) {
        int t = (tid >= off) ? sh[tid - off] : 0;
        __syncthreads();
        sh[tid] += t;
        __syncthreads();
    }
    if (tid < nb) g_boff[tid] = sh[tid] - v;
    if (tid == 127) g_rowoff[n] = sh[127];
}

__global__ void scan_add_kernel(int n) {
    int i = blockIdx.x * blockDim.x + threadIdx.x;
    if (i >= n) return;
    int val = g_rowtmp[i] + g_boff[i >> 10];
    g_rowoff[i] = val;
    g_cursor[i] = val;
}

__global__ void fill_kernel(const int* __restrict__ src, const int* __restrict__ dst, int E) {
    int i = blockIdx.x * blockDim.x + threadIdx.x;
    if (i >= E) return;
    int s = src[i], d = dst[i];
    int p = atomicAdd(&g_cursor[d], 1);
    g_esrc[p]  = s;
    g_enorm[p] = g_dinv[s] * g_dinv[d];
}

// -------- fused weight convert: all 5 weights -> B-format [n][k] fp16 -------
__global__ void convw_all_kernel(const float* __restrict__ Wu, const float* __restrict__ Wb,
                                 const float* __restrict__ W1, const float* __restrict__ W2,
                                 const float* __restrict__ W3,
                                 __half* __restrict__ ou, __half* __restrict__ ob,
                                 __half* __restrict__ o1, __half* __restrict__ o2,
                                 __half* __restrict__ o3)
{
    int idx = blockIdx.x * 256 + threadIdx.x;
    const float* W; __half* B; int K, NC, off;
    if      (idx < 131072) { W = Wu; B = ou; K = 1024; NC = 128; off = 0; }
    else if (idx < 262144) { W = Wb; B = ob; K = 1024; NC = 128; off = 131072; }
    else if (idx < 278528) { W = W1; B = o1; K = 128;  NC = 128; off = 262144; }
    else if (idx < 294912) { W = W2; B = o2; K = 128;  NC = 128; off = 278528; }
    else if (idx < 303104) { W = W3; B = o3; K = 128;  NC = 64;  off = 294912; }
    else return;
    int j = idx - off;
    int k = j / NC, n = j % NC;
    B[n * K + k] = __float2half_rn(W[j]);
}

// ---------------- common mma / cp helpers -----------------------------------
__device__ __forceinline__ void mma16816(float* c, const uint32_t* a, const uint32_t* b) {
    asm volatile(
        "mma.sync.aligned.m16n8k16.row.col.f32.f16.f16.f32 "
        "{%0,%1,%2,%3}, {%4,%5,%6,%7}, {%8,%9}, {%0,%1,%2,%3};\n"
        : "+f"(c[0]), "+f"(c[1]), "+f"(c[2]), "+f"(c[3])
        : "r"(a[0]), "r"(a[1]), "r"(a[2]), "r"(a[3]), "r"(b[0]), "r"(b[1]));
}
__device__ __forceinline__ void cvt_f4_h(float4 v, uint2& hi) {
    __half2 h0 = __floats2half2_rn(v.x, v.y);
    __half2 h1 = __floats2half2_rn(v.z, v.w);
    hi = make_uint2(*(uint32_t*)&h0, *(uint32_t*)&h1);
}
__device__ __forceinline__ void cp_async16(uint32_t saddr, const void* g) {
    asm volatile("cp.async.cg.shared.global [%0], [%1], 16;" :: "r"(saddr), "l"(g));
}
#define CP_COMMIT() asm volatile("cp.async.commit_group;" ::: "memory")
#define CP_WAIT0()  asm volatile("cp.async.wait_group 0;" ::: "memory")

// ---------------- projection GEMM: fp32 A -> fp16 convert, fp16 out ---------
// h16[nrows, 128] = fp16( x[nrows, 1024] @ (Wu|Wb) + (bu|bb) )
__global__ void __launch_bounds__(256, 2) gemm_proj_kernel(
    const float* __restrict__ A,
    const __half* __restrict__ Bh0, const __half* __restrict__ Bh1,
    const float* __restrict__ bias0, const float* __restrict__ bias1,
    __half* __restrict__ C16, int nrows, int KTOT, int userRows)
{
    constexpr int NCOL = 128;
    constexpr int STR = 40;
    constexpr int WN  = 64, NF = 8;
    constexpr int ASZ = 128 * STR;
    constexpr int BSZ = NCOL * STR;

    extern __shared__ uint16_t sm[];
    uint16_t* As = sm;                 // [2][ASZ]
    uint16_t* Bs = sm + 2 * ASZ;       // [2][BSZ]

    const int tid  = threadIdx.x;
    const int wid  = tid >> 5;
    const int lane = tid & 31;
    const int wm   = wid & 3;
    const int wn   = wid >> 2;
    const int g    = lane >> 2;
    const int t    = lane & 3;

    const int r0   = blockIdx.x * 128;
    const bool set0 = (r0 < userRows);
    const __half* Bh = set0 ? Bh0 : Bh1;
    const float* bias = set0 ? bias0 : bias1;

    float acc[2][NF][4];
#pragma unroll
    for (int mf = 0; mf < 2; mf++)
#pragma unroll
        for (int nf = 0; nf < NF; nf++)
#pragma unroll
            for (int i = 0; i < 4; i++) acc[mf][nf][i] = 0.f;

    const int arow[4] = { (tid + 0*256) >> 3, (tid + 1*256) >> 3,
                          (tid + 2*256) >> 3, (tid + 3*256) >> 3 };
    const int ac4 = (tid & 7) << 2;
    float4 areg[4];

    const int nchunk = KTOT >> 5;      // BK = 32

    auto loadA = [&](int c) {
        const int k0 = c << 5;
#pragma unroll
        for (int i = 0; i < 4; i++) {
            int row = arow[i];
            if (r0 + row < nrows)
                areg[i] = *(const float4*)(A + (size_t)(r0 + row) * KTOT + k0 + ac4);
            else
                areg[i] = make_float4(0.f, 0.f, 0.f, 0.f);
        }
    };
    auto storeA = [&](int buf) {
        uint16_t* a_s = As + buf * ASZ;
#pragma unroll
        for (int i = 0; i < 4; i++) {
            uint2 hi;
            cvt_f4_h(areg[i], hi);
            *(uint2*)&a_s[arow[i] * STR + ac4] = hi;
        }
    };
    auto cpB = [&](int c, int buf) {
        const int k0 = c << 5;
        uint16_t* b_s = Bs + buf * BSZ;
#pragma unroll
        for (int i = 0; i < 2; i++) {
            int idx = tid + i * 256;
            int n  = idx >> 2;
            int c8 = (idx & 3) << 3;
            uint32_t sh = (uint32_t)__cvta_generic_to_shared(&b_s[n * STR + c8]);
            cp_async16(sh, Bh + (size_t)n * KTOT + k0 + c8);
        }
        CP_COMMIT();
    };
    auto compute = [&](int buf) {
        uint16_t* a_s = As + buf * ASZ;
        uint16_t* b_s = Bs + buf * BSZ;
#pragma unroll
        for (int ks = 0; ks < 2; ks++) {
            uint32_t ah[2][4];
#pragma unroll
            for (int mf = 0; mf < 2; mf++) {
                int rb = (wm * 32 + mf * 16 + g) * STR + ks * 16 + t * 2;
                int r8 = rb + 8 * STR;
                ah[mf][0] = *(const uint32_t*)&a_s[rb];
                ah[mf][1] = *(const uint32_t*)&a_s[r8];
                ah[mf][2] = *(const uint32_t*)&a_s[rb + 8];
                ah[mf][3] = *(const uint32_t*)&a_s[r8 + 8];
            }
#pragma unroll
            for (int nf = 0; nf < NF; nf++) {
                int bb = (wn * WN + nf * 8 + g) * STR + ks * 16 + t * 2;
                uint32_t bh[2];
                bh[0] = *(const uint32_t*)&b_s[bb];
                bh[1] = *(const uint32_t*)&b_s[bb + 8];
#pragma unroll
                for (int mf = 0; mf < 2; mf++)
                    mma16816(acc[mf][nf], ah[mf], bh);
            }
        }
    };

    loadA(0);
    cpB(0, 0);
    storeA(0);
    CP_WAIT0();
    __syncthreads();

    for (int c = 0; c < nchunk; c++) {
        const int cur = c & 1, nxt = cur ^ 1;
        const bool more = (c + 1 < nchunk);
        if (more) {
            loadA(c + 1);
            cpB(c + 1, nxt);
        }
        compute(cur);
        __syncthreads();
        if (more) {
            storeA(nxt);
            CP_WAIT0();
            __syncthreads();
        }
    }

    // epilogue: fp16 output only
#pragma unroll
    for (int mf = 0; mf < 2; mf++) {
        int row = r0 + wm * 32 + mf * 16 + g;
#pragma unroll
        for (int nf = 0; nf < NF; nf++) {
            int col = wn * WN + nf * 8 + t * 2;
            float bx = bias[col], by = bias[col + 1];
            if (row < nrows) {
                float2 v = { acc[mf][nf][0] + bx, acc[mf][nf][1] + by };
                *(__half2*)(C16 + (size_t)row * NCOL + col) = __float22half2_rn(v);
            }
            if (row + 8 < nrows) {
                float2 v = { acc[mf][nf][2] + bx, acc[mf][nf][3] + by };
                *(__half2*)(C16 + (size_t)(row + 8) * NCOL + col) = __float22half2_rn(v);
            }
        }
    }
}

// ---------------- layer GEMM: fp16 A (cp.async), fp32+fp16 out --------------
// hw / hw16 [nrows, NCOL] = h16[nrows, 128] @ W
template <int NCOL>
__global__ void __launch_bounds__(256, 2) gemm_h16_kernel(
    const __half* __restrict__ A, const __half* __restrict__ Bh,
    float* __restrict__ C, __half* __restrict__ C16,
    int nrows, int KTOT)
{
    constexpr int STR = 40;
    constexpr int WN  = NCOL / 2;
    constexpr int NF  = WN / 8;
    constexpr int ASZ = 128 * STR;
    constexpr int BSZ = NCOL * STR;

    extern __shared__ uint16_t sm[];
    uint16_t* As = sm;                 // [2][ASZ]
    uint16_t* Bs = sm + 2 * ASZ;       // [2][BSZ]

    const int tid  = threadIdx.x;
    const int wid  = tid >> 5;
    const int lane = tid & 31;
    const int wm   = wid & 3;
    const int wn   = wid >> 2;
    const int g    = lane >> 2;
    const int t    = lane & 3;
    const int r0   = blockIdx.x * 128;

    float acc[2][NF][4];
#pragma unroll
    for (int mf = 0; mf < 2; mf++)
#pragma unroll
        for (int nf = 0; nf < NF; nf++)
#pragma unroll
            for (int i = 0; i < 4; i++) acc[mf][nf][i] = 0.f;

    const int nchunk = KTOT >> 5;      // BK = 32

    auto cpAB = [&](int c, int buf) {
        const int k0 = c << 5;
        uint16_t* a_s = As + buf * ASZ;
#pragma unroll
        for (int i = 0; i < 2; i++) {
            int idx = tid + i * 256;       // < 512
            int r  = idx >> 2;
            int c8 = (idx & 3) << 3;
            uint32_t sa = (uint32_t)__cvta_generic_to_shared(&a_s[r * STR + c8]);
            cp_async16(sa, A + (size_t)(r0 + r) * KTOT + k0 + c8);   // padded buffer
        }
        uint16_t* b_s = Bs + buf * BSZ;
#pragma unroll
        for (int i = 0; i < NCOL / 64; i++) {
            int idx = tid + i * 256;
            int n  = idx >> 2;
            int c8 = (idx & 3) << 3;
            uint32_t sb = (uint32_t)__cvta_generic_to_shared(&b_s[n * STR + c8]);
            cp_async16(sb, Bh + (size_t)n * KTOT + k0 + c8);
        }
        CP_COMMIT();
    };
    auto compute = [&](int buf) {
        uint16_t* a_s = As + buf * ASZ;
        uint16_t* b_s = Bs + buf * BSZ;
#pragma unroll
        for (int ks = 0; ks < 2; ks++) {
            uint32_t ah[2][4];
#pragma unroll
            for (int mf = 0; mf < 2; mf++) {
                int rb = (wm * 32 + mf * 16 + g) * STR + ks * 16 + t * 2;
                int r8 = rb + 8 * STR;
                ah[mf][0] = *(const uint32_t*)&a_s[rb];
                ah[mf][1] = *(const uint32_t*)&a_s[r8];
                ah[mf][2] = *(const uint32_t*)&a_s[rb + 8];
                ah[mf][3] = *(const uint32_t*)&a_s[r8 + 8];
            }
#pragma unroll
            for (int nf = 0; nf < NF; nf++) {
                int bb = (wn * WN + nf * 8 + g) * STR + ks * 16 + t * 2;
                uint32_t bh[2];
                bh[0] = *(const uint32_t*)&b_s[bb];
                bh[1] = *(const uint32_t*)&b_s[bb + 8];
#pragma unroll
                for (int mf = 0; mf < 2; mf++)
                    mma16816(acc[mf][nf], ah[mf], bh);
            }
        }
    };

    cpAB(0, 0);
    CP_WAIT0();
    __syncthreads();

    for (int c = 0; c < nchunk; c++) {
        const int cur = c & 1, nxt = cur ^ 1;
        const bool more = (c + 1 < nchunk);
        if (more) cpAB(c + 1, nxt);
        compute(cur);
        if (more) CP_WAIT0();
        __syncthreads();
    }

    // epilogue: fp32 + fp16 outputs (no bias; bias added in aggregation)
#pragma unroll
    for (int mf = 0; mf < 2; mf++) {
        int row = r0 + wm * 32 + mf * 16 + g;
#pragma unroll
        for (int nf = 0; nf < NF; nf++) {
            int col = wn * WN + nf * 8 + t * 2;
            if (row < nrows) {
                float2 v = { acc[mf][nf][0], acc[mf][nf][1] };
                *(float2*)(C + (size_t)row * NCOL + col) = v;
                *(__half2*)(C16 + (size_t)row * NCOL + col) = __float22half2_rn(v);
            }
            if (row + 8 < nrows) {
                float2 v = { acc[mf][nf][2], acc[mf][nf][3] };
                *(float2*)(C + (size_t)(row + 8) * NCOL + col) = v;
                *(__half2*)(C16 + (size_t)(row + 8) * NCOL + col) = __float22half2_rn(v);
            }
        }
    }
}

// ---------------- CSR aggregation -------------------------------------------
// self term fp32; neighbor gathers fp16 (8-way unrolled); output fp32 or fp16
template <int HD, bool RELU, bool OUT16>
__global__ void aggregate_kernel(const float* __restrict__ hw,
                                 const __half* __restrict__ hw16,
                                 const float* __restrict__ bias,
                                 float* __restrict__ outf,
                                 __half* __restrict__ out16, int n)
{
    constexpr int V = HD / 32;    // 4 or 2
    int gw = (blockIdx.x * blockDim.x + threadIdx.x) >> 5;
    if (gw >= n) return;
    int lane = threadIdx.x & 31;

    float acc[V];
    float di = g_dinv[gw];
    float sl = di * di;

    if (V == 4) {
        float4 r = *(const float4*)(hw + (size_t)gw * HD + lane * 4);
        acc[0] = r.x * sl; acc[1] = r.y * sl; acc[2] = r.z * sl; acc[3] = r.w * sl;
    } else {
        float2 r = *(const float2*)(hw + (size_t)gw * HD + lane * 2);
        acc[0] = r.x * sl; acc[1] = r.y * sl;
    }

    int e   = g_rowoff[gw];
    int end = g_rowoff[gw + 1];

    for (; e + 8 <= end; e += 8) {
        int   s[8];
        float nm[8];
#pragma unroll
        for (int j = 0; j < 8; j++) {
            s[j]  = __ldg(&g_esrc[e + j]);
            nm[j] = __ldg(&g_enorm[e + j]);
        }
        if (V == 4) {
            int2 r[8];
#pragma unroll
            for (int j = 0; j < 8; j++)
                r[j] = *(const int2*)(hw16 + (size_t)s[j] * HD + lane * 4);
#pragma unroll
            for (int j = 0; j < 8; j++) {
                float2 a = __half22float2(*(__half2*)&r[j].x);
                float2 b = __half22float2(*(__half2*)&r[j].y);
                acc[0] += a.x * nm[j]; acc[1] += a.y * nm[j];
                acc[2] += b.x * nm[j]; acc[3] += b.y * nm[j];
            }
        } else {
            int r[8];
#pragma unroll
            for (int j = 0; j < 8; j++)
                r[j] = *(const int*)(hw16 + (size_t)s[j] * HD + lane * 2);
#pragma unroll
            for (int j = 0; j < 8; j++) {
                float2 a = __half22float2(*(__half2*)&r[j]);
                acc[0] += a.x * nm[j]; acc[1] += a.y * nm[j];
            }
        }
    }
    for (; e < end; e++) {
        int   s  = __ldg(&g_esrc[e]);
        float nm = __ldg(&g_enorm[e]);
        if (V == 4) {
            int2 raw = *(const int2*)(hw16 + (size_t)s * HD + lane * 4);
            float2 f0 = __half22float2(*(__half2*)&raw.x);
            float2 f1 = __half22float2(*(__half2*)&raw.y);
            acc[0] += f0.x * nm; acc[1] += f0.y * nm;
            acc[2] += f1.x * nm; acc[3] += f1.y * nm;
        } else {
            int raw = *(const int*)(hw16 + (size_t)s * HD + lane * 2);
            float2 f0 = __half22float2(*(__half2*)&raw);
            acc[0] += f0.x * nm; acc[1] += f0.y * nm;
        }
    }

#pragma unroll
    for (int v = 0; v < V; v++) {
        float val = acc[v] + bias[lane * V + v];
        if (RELU) val = fmaxf(val, 0.f);
        acc[v] = val;
    }
    if (OUT16) {
        if (V == 4) {
            __half2 h0 = __floats2half2_rn(acc[0], acc[1]);
            __half2 h1 = __floats2half2_rn(acc[2], acc[3]);
            int2 o; o.x = *(int*)&h0; o.y = *(int*)&h1;
            *(int2*)(out16 + (size_t)gw * HD + lane * 4) = o;
        } else {
            __half2 h0 = __floats2half2_rn(acc[0], acc[1]);
            *(int*)(out16 + (size_t)gw * HD + lane * 2) = *(int*)&h0;
        }
    } else {
        if (V == 4) {
            float4 o; o.x = acc[0]; o.y = acc[1]; o.z = acc[2]; o.w = acc[3];
            *(float4*)(outf + (size_t)gw * HD + lane * 4) = o;
        } else {
            float2 o; o.x = acc[0]; o.y = acc[1];
            *(float2*)(outf + (size_t)gw * HD + lane * 2) = o;
        }
    }
}

// ---------------- launch ----------------------------------------------------
extern "C" void kernel_launch(void* const* d_in, const int* in_sizes, int n_in,
                              void* d_out, int out_size)
{
    const float* x  = (const float*)d_in[0];
    const int*   ei = (const int*)  d_in[1];
    const float* Wu = (const float*)d_in[2];
    const float* bu = (const float*)d_in[3];
    const float* Wb = (const float*)d_in[4];
    const float* bb = (const float*)d_in[5];
    const float* W1 = (const float*)d_in[6];
    const float* b1 = (const float*)d_in[7];
    const float* W2 = (const float*)d_in[8];
    const float* b2 = (const float*)d_in[9];
    const float* W3 = (const float*)d_in[10];
    const float* b3 = (const float*)d_in[11];

    const int N = in_sizes[0] / FEAT;     // 101024
    const int E = in_sizes[1] / 2;        // 2000000
    const int userRows = 1024;

    float *hw_ptr;
    __half *h16_ptr, *hw16_ptr;
    cudaGetSymbolAddress((void**)&h16_ptr,  g_h16);
    cudaGetSymbolAddress((void**)&hw_ptr,   g_hw);
    cudaGetSymbolAddress((void**)&hw16_ptr, g_hw16);

    __half *bh_u, *bh_b, *bh_1, *bh_2, *bh_3;
    cudaGetSymbolAddress((void**)&bh_u, g_bh_u);
    cudaGetSymbolAddress((void**)&bh_b, g_bh_b);
    cudaGetSymbolAddress((void**)&bh_1, g_bh_1);
    cudaGetSymbolAddress((void**)&bh_2, g_bh_2);
    cudaGetSymbolAddress((void**)&bh_3, g_bh_3);

    const int* src = ei;
    const int* dst = ei + E;

    // dynamic smem opt-in
    constexpr int SMEM_P   = (2 * 128 * 40 + 2 * 128 * 40) * 2;  // 40960 B
    constexpr int SMEM_L128 = SMEM_P;                            // 40960 B
    constexpr int SMEM_L64  = (2 * 128 * 40 + 2 * 64 * 40) * 2;  // 30720 B
    cudaFuncSetAttribute((const void*)gemm_proj_kernel,      cudaFuncAttributeMaxDynamicSharedMemorySize, SMEM_P);
    cudaFuncSetAttribute((const void*)gemm_h16_kernel<128>,  cudaFuncAttributeMaxDynamicSharedMemorySize, SMEM_L128);
    cudaFuncSetAttribute((const void*)gemm_h16_kernel<64>,   cudaFuncAttributeMaxDynamicSharedMemorySize, SMEM_L64);

    // one-time side-stream/event setup (host resources; identical work per call)
    static cudaStream_t s2 = 0;
    static cudaEvent_t evFork = 0, evJoin = 0;
    static int sinit = 0;
    if (!sinit) {
        sinit = 1;
        if (cudaStreamCreateWithFlags(&s2, cudaStreamNonBlocking) != cudaSuccess) s2 = 0;
        if (s2) {
            if (cudaEventCreateWithFlags(&evFork, cudaEventDisableTiming) != cudaSuccess ||
                cudaEventCreateWithFlags(&evJoin, cudaEventDisableTiming) != cudaSuccess)
                s2 = 0;
        }
    }
    const bool fork = (s2 != 0);
    cudaStream_t sc = fork ? s2 : 0;

    if (fork) {
        cudaEventRecord(evFork, 0);
        cudaStreamWaitEvent(s2, evFork, 0);
    }

    // 1) degree / CSR build (side stream — overlaps with convw + GEMMs)
    zero_cnt_kernel<<<(N + 255) / 256, 256, 0, sc>>>(N);
    count_kernel<<<(E + 255) / 256, 256, 0, sc>>>(dst, E);
    dinv_kernel<<<(N + 255) / 256, 256, 0, sc>>>(N);
    int nb = (N + 1023) / 1024;
    scan_block_kernel<<<nb, 1024, 0, sc>>>(N);
    scan_bsum_kernel<<<1, 128, 0, sc>>>(nb, N);
    scan_add_kernel<<<(N + 255) / 256, 256, 0, sc>>>(N);
    fill_kernel<<<(E + 255) / 256, 256, 0, sc>>>(src, dst, E);
    if (fork) cudaEventRecord(evJoin, s2);

    // 2) fused weight conversion — main stream
    convw_all_kernel<<<(303104 + 255) / 256, 256>>>(Wu, Wb, W1, W2, W3,
                                                    bh_u, bh_b, bh_1, bh_2, bh_3);

    int gemmBlocks = (N + 127) / 128;
    int aggBlocks  = (N + 7) / 8;

    // 3) projection: h16 = fp16( x @ (Wu|Wb) + (bu|bb) )
    gemm_proj_kernel<<<gemmBlocks, 256, SMEM_P>>>(
        x, bh_u, bh_b, bu, bb, h16_ptr, N, FEAT, userRows);

    // 4) layer 1: hw = h16 @ W1 ; h16 = fp16(relu(agg(hw) + b1))
    gemm_h16_kernel<128><<<gemmBlocks, 256, SMEM_L128>>>(
        h16_ptr, bh_1, hw_ptr, hw16_ptr, N, H0);

    if (fork) cudaStreamWaitEvent(0, evJoin, 0);   // CSR ready before aggregation
    aggregate_kernel<128, true, true><<<aggBlocks, 256>>>(
        hw_ptr, hw16_ptr, b1, nullptr, h16_ptr, N);

    // 5) layer 2
    gemm_h16_kernel<128><<<gemmBlocks, 256, SMEM_L128>>>(
        h16_ptr, bh_2, hw_ptr, hw16_ptr, N, H0);
    aggregate_kernel<128, true, true><<<aggBlocks, 256>>>(
        hw_ptr, hw16_ptr, b2, nullptr, h16_ptr, N);

    // 6) layer 3 (out dim 64, no relu) -> d_out fp32
    gemm_h16_kernel<64><<<gemmBlocks, 256, SMEM_L64>>>(
        h16_ptr, bh_3, hw_ptr, hw16_ptr, N, H0);
    aggregate_kernel<64, false, false><<<aggBlocks, 256>>>(
        hw_ptr, hw16_ptr, b3, (float*)d_out, nullptr, N);
}

// round 16
// speedup vs baseline: 3.4817x; 1.0802x over previous
#include <cuda_runtime.h>
#include <cuda_bf16.h>
#include <cuda_fp16.h>
#include <cstdint>

// Problem constants (fixed by the dataset)
#define MAXN 101024
#define MAXE 2000000
#define FEAT 1024
#define H0 128

// ---------------- scratch (device globals; no allocation allowed) ----------
__device__ __half g_h16[(size_t)(MAXN + 128) * H0]; // node features, fp16 (padded tail)
__device__ __half g_hw16[(size_t)MAXN * H0]; // h @ W (fp16: gather + self table)
__device__ float g_dinv[MAXN];
__device__ int   g_cnt[MAXN];
__device__ int   g_rowoff[MAXN + 1];
__device__ int   g_cursor[MAXN];
__device__ int   g_rowtmp[MAXN];
__device__ int   g_bsum[128];
__device__ int   g_boff[128];
__device__ int   g_esrc[MAXE];
__device__ float g_enorm[MAXE];

// fp16 weight buffers, transposed to B-format [n][k]
__device__ __half g_bh_u[128 * 1024];
__device__ __half g_bh_b[128 * 1024];
__device__ __half g_bh_1[128 * 128];
__device__ __half g_bh_2[128 * 128];
__device__ __half g_bh_3[64 * 128];

// ---------------- CSR construction ----------------------------------------
__global__ void zero_cnt_kernel(int n) {
    int i = blockIdx.x * blockDim.x + threadIdx.x;
    if (i < n) g_cnt[i] = 0;
}

__global__ void count_kernel(const int* __restrict__ dst, int E) {
    int i = blockIdx.x * blockDim.x + threadIdx.x;
    if (i < E) atomicAdd(&g_cnt[dst[i]], 1);
}

__global__ void dinv_kernel(int n) {
    int i = blockIdx.x * blockDim.x + threadIdx.x;
    if (i < n) g_dinv[i] = rsqrtf((float)(g_cnt[i] + 1));  // +1 self loop
}

__global__ void scan_block_kernel(int n) {
    __shared__ int sh[1024];
    int tid = threadIdx.x;
    int i = blockIdx.x * 1024 + tid;
    int v = (i < n) ? g_cnt[i] : 0;
    sh[tid] = v;
    __syncthreads();
    for (int off = 1; off < 1024; off <<= 1) {
        int t = (tid >= off) ? sh[tid - off] : 0;
        __syncthreads();
        sh[tid] += t;
        __syncthreads();
    }
    if (i < n) g_rowtmp[i] = sh[tid] - v;
    if (tid == 1023) g_bsum[blockIdx.x] = sh[1023];
}

__global__ void scan_bsum_kernel(int nb, int n) {
    __shared__ int sh[128];
    int tid = threadIdx.x;
    int v = (tid < nb) ? g_bsum[tid] : 0;
    sh[tid] = v;
    __syncthreads();
    for (int off = 1; off < 128; off <<= 1) {
        int t = (tid >= off) ? sh[tid - off] : 0;
        __syncthreads();
        sh[tid] += t;
        __syncthreads();
    }
    if (tid < nb) g_boff[tid] = sh[tid] - v;
    if (tid == 127) g_rowoff[n] = sh[127];
}

__global__ void scan_add_kernel(int n) {
    int i = blockIdx.x * blockDim.x + threadIdx.x;
    if (i >= n) return;
    int val = g_rowtmp[i] + g_boff[i >> 10];
    g_rowoff[i] = val;
    g_cursor[i] = val;
}

__global__ void fill_kernel(const int* __restrict__ src, const int* __restrict__ dst, int E) {
    int i = blockIdx.x * blockDim.x + threadIdx.x;
    if (i >= E) return;
    int s = src[i], d = dst[i];
    int p = atomicAdd(&g_cursor[d], 1);
    g_esrc[p]  = s;
    g_enorm[p] = g_dinv[s] * g_dinv[d];
}

// -------- fused weight convert: all 5 weights -> B-format [n][k] fp16 -------
__global__ void convw_all_kernel(const float* __restrict__ Wu, const float* __restrict__ Wb,
                                 const float* __restrict__ W1, const float* __restrict__ W2,
                                 const float* __restrict__ W3,
                                 __half* __restrict__ ou, __half* __restrict__ ob,
                                 __half* __restrict__ o1, __half* __restrict__ o2,
                                 __half* __restrict__ o3)
{
    int idx = blockIdx.x * 256 + threadIdx.x;
    const float* W; __half* B; int K, NC, off;
    if      (idx < 131072) { W = Wu; B = ou; K = 1024; NC = 128; off = 0; }
    else if (idx < 262144) { W = Wb; B = ob; K = 1024; NC = 128; off = 131072; }
    else if (idx < 278528) { W = W1; B = o1; K = 128;  NC = 128; off = 262144; }
    else if (idx < 294912) { W = W2; B = o2; K = 128;  NC = 128; off = 278528; }
    else if (idx < 303104) { W = W3; B = o3; K = 128;  NC = 64;  off = 294912; }
    else return;
    int j = idx - off;
    int k = j / NC, n = j % NC;
    B[n * K + k] = __float2half_rn(W[j]);
}

// ---------------- common mma / cp helpers -----------------------------------
__device__ __forceinline__ void mma16816(float* c, const uint32_t* a, const uint32_t* b) {
    asm volatile(
        "mma.sync.aligned.m16n8k16.row.col.f32.f16.f16.f32 "
        "{%0,%1,%2,%3}, {%4,%5,%6,%7}, {%8,%9}, {%0,%1,%2,%3};\n"
        : "+f"(c[0]), "+f"(c[1]), "+f"(c[2]), "+f"(c[3])
        : "r"(a[0]), "r"(a[1]), "r"(a[2]), "r"(a[3]), "r"(b[0]), "r"(b[1]));
}
__device__ __forceinline__ void cvt_f4_h(float4 v, uint2& hi) {
    __half2 h0 = __floats2half2_rn(v.x, v.y);
    __half2 h1 = __floats2half2_rn(v.z, v.w);
    hi = make_uint2(*(uint32_t*)&h0, *(uint32_t*)&h1);
}
__device__ __forceinline__ void cp_async16(uint32_t saddr, const void* g) {
    asm volatile("cp.async.cg.shared.global [%0], [%1], 16;" :: "r"(saddr), "l"(g));
}
#define CP_COMMIT() asm volatile("cp.async.commit_group;" ::: "memory")
#define CP_WAIT0()  asm volatile("cp.async.wait_group 0;" ::: "memory")

// ---------------- projection GEMM: fp32 A -> fp16 convert, fp16 out ---------
// h16[nrows, 128] = fp16( x[nrows, 1024] @ (Wu|Wb) + (bu|bb) )
__global__ void __launch_bounds__(256, 2) gemm_proj_kernel(
    const float* __restrict__ A,
    const __half* __restrict__ Bh0, const __half* __restrict__ Bh1,
    const float* __restrict__ bias0, const float* __restrict__ bias1,
    __half* __restrict__ C16, int nrows, int KTOT, int userRows)
{
    constexpr int NCOL = 128;
    constexpr int STR = 40;
    constexpr int WN  = 64, NF = 8;
    constexpr int ASZ = 128 * STR;
    constexpr int BSZ = NCOL * STR;

    extern __shared__ uint16_t sm[];
    uint16_t* As = sm;                 // [2][ASZ]
    uint16_t* Bs = sm + 2 * ASZ;       // [2][BSZ]

    const int tid  = threadIdx.x;
    const int wid  = tid >> 5;
    const int lane = tid & 31;
    const int wm   = wid & 3;
    const int wn   = wid >> 2;
    const int g    = lane >> 2;
    const int t    = lane & 3;

    const int r0   = blockIdx.x * 128;
    const bool set0 = (r0 < userRows);
    const __half* Bh = set0 ? Bh0 : Bh1;
    const float* bias = set0 ? bias0 : bias1;

    float acc[2][NF][4];
#pragma unroll
    for (int mf = 0; mf < 2; mf++)
#pragma unroll
        for (int nf = 0; nf < NF; nf++)
#pragma unroll
            for (int i = 0; i < 4; i++) acc[mf][nf][i] = 0.f;

    const int arow[4] = { (tid + 0*256) >> 3, (tid + 1*256) >> 3,
                          (tid + 2*256) >> 3, (tid + 3*256) >> 3 };
    const int ac4 = (tid & 7) << 2;
    float4 areg[4];

    const int nchunk = KTOT >> 5;      // BK = 32

    auto loadA = [&](int c) {
        const int k0 = c << 5;
#pragma unroll
        for (int i = 0; i < 4; i++) {
            int row = arow[i];
            if (r0 + row < nrows)
                areg[i] = *(const float4*)(A + (size_t)(r0 + row) * KTOT + k0 + ac4);
            else
                areg[i] = make_float4(0.f, 0.f, 0.f, 0.f);
        }
    };
    auto storeA = [&](int buf) {
        uint16_t* a_s = As + buf * ASZ;
#pragma unroll
        for (int i = 0; i < 4; i++) {
            uint2 hi;
            cvt_f4_h(areg[i], hi);
            *(uint2*)&a_s[arow[i] * STR + ac4] = hi;
        }
    };
    auto cpB = [&](int c, int buf) {
        const int k0 = c << 5;
        uint16_t* b_s = Bs + buf * BSZ;
#pragma unroll
        for (int i = 0; i < 2; i++) {
            int idx = tid + i * 256;
            int n  = idx >> 2;
            int c8 = (idx & 3) << 3;
            uint32_t sh = (uint32_t)__cvta_generic_to_shared(&b_s[n * STR + c8]);
            cp_async16(sh, Bh + (size_t)n * KTOT + k0 + c8);
        }
        CP_COMMIT();
    };
    auto compute = [&](int buf) {
        uint16_t* a_s = As + buf * ASZ;
        uint16_t* b_s = Bs + buf * BSZ;
#pragma unroll
        for (int ks = 0; ks < 2; ks++) {
            uint32_t ah[2][4];
#pragma unroll
            for (int mf = 0; mf < 2; mf++) {
                int rb = (wm * 32 + mf * 16 + g) * STR + ks * 16 + t * 2;
                int r8 = rb + 8 * STR;
                ah[mf][0] = *(const uint32_t*)&a_s[rb];
                ah[mf][1] = *(const uint32_t*)&a_s[r8];
                ah[mf][2] = *(const uint32_t*)&a_s[rb + 8];
                ah[mf][3] = *(const uint32_t*)&a_s[r8 + 8];
            }
#pragma unroll
            for (int nf = 0; nf < NF; nf++) {
                int bb = (wn * WN + nf * 8 + g) * STR + ks * 16 + t * 2;
                uint32_t bh[2];
                bh[0] = *(const uint32_t*)&b_s[bb];
                bh[1] = *(const uint32_t*)&b_s[bb + 8];
#pragma unroll
                for (int mf = 0; mf < 2; mf++)
                    mma16816(acc[mf][nf], ah[mf], bh);
            }
        }
    };

    loadA(0);
    cpB(0, 0);
    storeA(0);
    CP_WAIT0();
    __syncthreads();

    for (int c = 0; c < nchunk; c++) {
        const int cur = c & 1, nxt = cur ^ 1;
        const bool more = (c + 1 < nchunk);
        if (more) {
            loadA(c + 1);
            cpB(c + 1, nxt);
        }
        compute(cur);
        __syncthreads();
        if (more) {
            storeA(nxt);
            CP_WAIT0();
            __syncthreads();
        }
    }

    // epilogue: fp16 output only
#pragma unroll
    for (int mf = 0; mf < 2; mf++) {
        int row = r0 + wm * 32 + mf * 16 + g;
#pragma unroll
        for (int nf = 0; nf < NF; nf++) {
            int col = wn * WN + nf * 8 + t * 2;
            float bx = bias[col], by = bias[col + 1];
            if (row < nrows) {
                float2 v = { acc[mf][nf][0] + bx, acc[mf][nf][1] + by };
                *(__half2*)(C16 + (size_t)row * NCOL + col) = __float22half2_rn(v);
            }
            if (row + 8 < nrows) {
                float2 v = { acc[mf][nf][2] + bx, acc[mf][nf][3] + by };
                *(__half2*)(C16 + (size_t)(row + 8) * NCOL + col) = __float22half2_rn(v);
            }
        }
    }
}

// ---------------- layer GEMM: fp16 A (cp.async), fp16 out only --------------
// hw16[nrows, NCOL] = h16[nrows, 128] @ W
template <int NCOL>
__global__ void __launch_bounds__(256, 2) gemm_h16_kernel(
    const __half* __restrict__ A, const __half* __restrict__ Bh,
    __half* __restrict__ C16, int nrows, int KTOT)
{
    constexpr int STR = 40;
    constexpr int WN  = NCOL / 2;
    constexpr int NF  = WN / 8;
    constexpr int ASZ = 128 * STR;
    constexpr int BSZ = NCOL * STR;

    extern __shared__ uint16_t sm[];
    uint16_t* As = sm;                 // [2][ASZ]
    uint16_t* Bs = sm + 2 * ASZ;       // [2][BSZ]

    const int tid  = threadIdx.x;
    const int wid  = tid >> 5;
    const int lane = tid & 31;
    const int wm   = wid & 3;
    const int wn   = wid >> 2;
    const int g    = lane >> 2;
    const int t    = lane & 3;
    const int r0   = blockIdx.x * 128;

    float acc[2][NF][4];
#pragma unroll
    for (int mf = 0; mf < 2; mf++)
#pragma unroll
        for (int nf = 0; nf < NF; nf++)
#pragma unroll
            for (int i = 0; i < 4; i++) acc[mf][nf][i] = 0.f;

    const int nchunk = KTOT >> 5;      // BK = 32

    auto cpAB = [&](int c, int buf) {
        const int k0 = c << 5;
        uint16_t* a_s = As + buf * ASZ;
#pragma unroll
        for (int i = 0; i < 2; i++) {
            int idx = tid + i * 256;       // < 512
            int r  = idx >> 2;
            int c8 = (idx & 3) << 3;
            uint32_t sa = (uint32_t)__cvta_generic_to_shared(&a_s[r * STR + c8]);
            cp_async16(sa, A + (size_t)(r0 + r) * KTOT + k0 + c8);   // padded buffer
        }
        uint16_t* b_s = Bs + buf * BSZ;
#pragma unroll
        for (int i = 0; i < NCOL / 64; i++) {
            int idx = tid + i * 256;
            int n  = idx >> 2;
            int c8 = (idx & 3) << 3;
            uint32_t sb = (uint32_t)__cvta_generic_to_shared(&b_s[n * STR + c8]);
            cp_async16(sb, Bh + (size_t)n * KTOT + k0 + c8);
        }
        CP_COMMIT();
    };
    auto compute = [&](int buf) {
        uint16_t* a_s = As + buf * ASZ;
        uint16_t* b_s = Bs + buf * BSZ;
#pragma unroll
        for (int ks = 0; ks < 2; ks++) {
            uint32_t ah[2][4];
#pragma unroll
            for (int mf = 0; mf < 2; mf++) {
                int rb = (wm * 32 + mf * 16 + g) * STR + ks * 16 + t * 2;
                int r8 = rb + 8 * STR;
                ah[mf][0] = *(const uint32_t*)&a_s[rb];
                ah[mf][1] = *(const uint32_t*)&a_s[r8];
                ah[mf][2] = *(const uint32_t*)&a_s[rb + 8];
                ah[mf][3] = *(const uint32_t*)&a_s[r8 + 8];
            }
#pragma unroll
            for (int nf = 0; nf < NF; nf++) {
                int bb = (wn * WN + nf * 8 + g) * STR + ks * 16 + t * 2;
                uint32_t bh[2];
                bh[0] = *(const uint32_t*)&b_s[bb];
                bh[1] = *(const uint32_t*)&b_s[bb + 8];
#pragma unroll
                for (int mf = 0; mf < 2; mf++)
                    mma16816(acc[mf][nf], ah[mf], bh);
            }
        }
    };

    cpAB(0, 0);
    CP_WAIT0();
    __syncthreads();

    for (int c = 0; c < nchunk; c++) {
        const int cur = c & 1, nxt = cur ^ 1;
        const bool more = (c + 1 < nchunk);
        if (more) cpAB(c + 1, nxt);
        compute(cur);
        if (more) CP_WAIT0();
        __syncthreads();
    }

    // epilogue: fp16 output only (no bias; bias added in aggregation)
#pragma unroll
    for (int mf = 0; mf < 2; mf++) {
        int row = r0 + wm * 32 + mf * 16 + g;
#pragma unroll
        for (int nf = 0; nf < NF; nf++) {
            int col = wn * WN + nf * 8 + t * 2;
            if (row < nrows) {
                float2 v = { acc[mf][nf][0], acc[mf][nf][1] };
                *(__half2*)(C16 + (size_t)row * NCOL + col) = __float22half2_rn(v);
            }
            if (row + 8 < nrows) {
                float2 v = { acc[mf][nf][2], acc[mf][nf][3] };
                *(__half2*)(C16 + (size_t)(row + 8) * NCOL + col) = __float22half2_rn(v);
            }
        }
    }
}

// ---------------- CSR aggregation -------------------------------------------
// self + neighbor terms from fp16 hw16 (8-way unrolled); out fp32 or fp16
template <int HD, bool RELU, bool OUT16>
__global__ void aggregate_kernel(const __half* __restrict__ hw16,
                                 const float* __restrict__ bias,
                                 float* __restrict__ outf,
                                 __half* __restrict__ out16, int n)
{
    constexpr int V = HD / 32;    // 4 or 2
    int gw = (blockIdx.x * blockDim.x + threadIdx.x) >> 5;
    if (gw >= n) return;
    int lane = threadIdx.x & 31;

    float acc[V];
    float di = g_dinv[gw];
    float sl = di * di;

    if (V == 4) {
        int2 raw = *(const int2*)(hw16 + (size_t)gw * HD + lane * 4);
        float2 f0 = __half22float2(*(__half2*)&raw.x);
        float2 f1 = __half22float2(*(__half2*)&raw.y);
        acc[0] = f0.x * sl; acc[1] = f0.y * sl;
        acc[2] = f1.x * sl; acc[3] = f1.y * sl;
    } else {
        int raw = *(const int*)(hw16 + (size_t)gw * HD + lane * 2);
        float2 f0 = __half22float2(*(__half2*)&raw);
        acc[0] = f0.x * sl; acc[1] = f0.y * sl;
    }

    int e   = g_rowoff[gw];
    int end = g_rowoff[gw + 1];

    for (; e + 8 <= end; e += 8) {
        int   s[8];
        float nm[8];
#pragma unroll
        for (int j = 0; j < 8; j++) {
            s[j]  = __ldg(&g_esrc[e + j]);
            nm[j] = __ldg(&g_enorm[e + j]);
        }
        if (V == 4) {
            int2 r[8];
#pragma unroll
            for (int j = 0; j < 8; j++)
                r[j] = *(const int2*)(hw16 + (size_t)s[j] * HD + lane * 4);
#pragma unroll
            for (int j = 0; j < 8; j++) {
                float2 a = __half22float2(*(__half2*)&r[j].x);
                float2 b = __half22float2(*(__half2*)&r[j].y);
                acc[0] += a.x * nm[j]; acc[1] += a.y * nm[j];
                acc[2] += b.x * nm[j]; acc[3] += b.y * nm[j];
            }
        } else {
            int r[8];
#pragma unroll
            for (int j = 0; j < 8; j++)
                r[j] = *(const int*)(hw16 + (size_t)s[j] * HD + lane * 2);
#pragma unroll
            for (int j = 0; j < 8; j++) {
                float2 a = __half22float2(*(__half2*)&r[j]);
                acc[0] += a.x * nm[j]; acc[1] += a.y * nm[j];
            }
        }
    }
    for (; e < end; e++) {
        int   s  = __ldg(&g_esrc[e]);
        float nm = __ldg(&g_enorm[e]);
        if (V == 4) {
            int2 raw = *(const int2*)(hw16 + (size_t)s * HD + lane * 4);
            float2 f0 = __half22float2(*(__half2*)&raw.x);
            float2 f1 = __half22float2(*(__half2*)&raw.y);
            acc[0] += f0.x * nm; acc[1] += f0.y * nm;
            acc[2] += f1.x * nm; acc[3] += f1.y * nm;
        } else {
            int raw = *(const int*)(hw16 + (size_t)s * HD + lane * 2);
            float2 f0 = __half22float2(*(__half2*)&raw);
            acc[0] += f0.x * nm; acc[1] += f0.y * nm;
        }
    }

#pragma unroll
    for (int v = 0; v < V; v++) {
        float val = acc[v] + bias[lane * V + v];
        if (RELU) val = fmaxf(val, 0.f);
        acc[v] = val;
    }
    if (OUT16) {
        if (V == 4) {
            __half2 h0 = __floats2half2_rn(acc[0], acc[1]);
            __half2 h1 = __floats2half2_rn(acc[2], acc[3]);
            int2 o; o.x = *(int*)&h0; o.y = *(int*)&h1;
            *(int2*)(out16 + (size_t)gw * HD + lane * 4) = o;
        } else {
            __half2 h0 = __floats2half2_rn(acc[0], acc[1]);
            *(int*)(out16 + (size_t)gw * HD + lane * 2) = *(int*)&h0;
        }
    } else {
        if (V == 4) {
            float4 o; o.x = acc[0]; o.y = acc[1]; o.z = acc[2]; o.w = acc[3];
            *(float4*)(outf + (size_t)gw * HD + lane * 4) = o;
        } else {
            float2 o; o.x = acc[0]; o.y = acc[1];
            *(float2*)(outf + (size_t)gw * HD + lane * 2) = o;
        }
    }
}

// ---------------- launch ----------------------------------------------------
extern "C" void kernel_launch(void* const* d_in, const int* in_sizes, int n_in,
                              void* d_out, int out_size)
{
    const float* x  = (const float*)d_in[0];
    const int*   ei = (const int*)  d_in[1];
    const float* Wu = (const float*)d_in[2];
    const float* bu = (const float*)d_in[3];
    const float* Wb = (const float*)d_in[4];
    const float* bb = (const float*)d_in[5];
    const float* W1 = (const float*)d_in[6];
    const float* b1 = (const float*)d_in[7];
    const float* W2 = (const float*)d_in[8];
    const float* b2 = (const float*)d_in[9];
    const float* W3 = (const float*)d_in[10];
    const float* b3 = (const float*)d_in[11];

    const int N = in_sizes[0] / FEAT;     // 101024
    const int E = in_sizes[1] / 2;        // 2000000
    const int userRows = 1024;

    __half *h16_ptr, *hw16_ptr;
    cudaGetSymbolAddress((void**)&h16_ptr,  g_h16);
    cudaGetSymbolAddress((void**)&hw16_ptr, g_hw16);

    __half *bh_u, *bh_b, *bh_1, *bh_2, *bh_3;
    cudaGetSymbolAddress((void**)&bh_u, g_bh_u);
    cudaGetSymbolAddress((void**)&bh_b, g_bh_b);
    cudaGetSymbolAddress((void**)&bh_1, g_bh_1);
    cudaGetSymbolAddress((void**)&bh_2, g_bh_2);
    cudaGetSymbolAddress((void**)&bh_3, g_bh_3);

    const int* src = ei;
    const int* dst = ei + E;

    // dynamic smem opt-in
    constexpr int SMEM_P    = (2 * 128 * 40 + 2 * 128 * 40) * 2;  // 40960 B
    constexpr int SMEM_L128 = SMEM_P;                             // 40960 B
    constexpr int SMEM_L64  = (2 * 128 * 40 + 2 * 64 * 40) * 2;   // 30720 B
    cudaFuncSetAttribute((const void*)gemm_proj_kernel,     cudaFuncAttributeMaxDynamicSharedMemorySize, SMEM_P);
    cudaFuncSetAttribute((const void*)gemm_h16_kernel<128>, cudaFuncAttributeMaxDynamicSharedMemorySize, SMEM_L128);
    cudaFuncSetAttribute((const void*)gemm_h16_kernel<64>,  cudaFuncAttributeMaxDynamicSharedMemorySize, SMEM_L64);

    // one-time side-stream/event setup (host resources; identical work per call)
    static cudaStream_t s2 = 0;
    static cudaEvent_t evFork = 0, evJoin = 0;
    static int sinit = 0;
    if (!sinit) {
        sinit = 1;
        if (cudaStreamCreateWithFlags(&s2, cudaStreamNonBlocking) != cudaSuccess) s2 = 0;
        if (s2) {
            if (cudaEventCreateWithFlags(&evFork, cudaEventDisableTiming) != cudaSuccess ||
                cudaEventCreateWithFlags(&evJoin, cudaEventDisableTiming) != cudaSuccess)
                s2 = 0;
        }
    }
    const bool fork = (s2 != 0);
    cudaStream_t sc = fork ? s2 : 0;

    if (fork) {
        cudaEventRecord(evFork, 0);
        cudaStreamWaitEvent(s2, evFork, 0);
    }

    // 1) degree / CSR build (side stream — overlaps with convw + GEMMs)
    zero_cnt_kernel<<<(N + 255) / 256, 256, 0, sc>>>(N);
    count_kernel<<<(E + 255) / 256, 256, 0, sc>>>(dst, E);
    dinv_kernel<<<(N + 255) / 256, 256, 0, sc>>>(N);
    int nb = (N + 1023) / 1024;
    scan_block_kernel<<<nb, 1024, 0, sc>>>(N);
    scan_bsum_kernel<<<1, 128, 0, sc>>>(nb, N);
    scan_add_kernel<<<(N + 255) / 256, 256, 0, sc>>>(N);
    fill_kernel<<<(E + 255) / 256, 256, 0, sc>>>(src, dst, E);
    if (fork) cudaEventRecord(evJoin, s2);

    // 2) fused weight conversion — main stream
    convw_all_kernel<<<(303104 + 255) / 256, 256>>>(Wu, Wb, W1, W2, W3,
                                                    bh_u, bh_b, bh_1, bh_2, bh_3);

    int gemmBlocks = (N + 127) / 128;
    int aggBlocks  = (N + 7) / 8;

    // 3) projection: h16 = fp16( x @ (Wu|Wb) + (bu|bb) )
    gemm_proj_kernel<<<gemmBlocks, 256, SMEM_P>>>(
        x, bh_u, bh_b, bu, bb, h16_ptr, N, FEAT, userRows);

    // 4) layer 1: hw16 = h16 @ W1 ; h16 = fp16(relu(agg(hw16) + b1))
    gemm_h16_kernel<128><<<gemmBlocks, 256, SMEM_L128>>>(
        h16_ptr, bh_1, hw16_ptr, N, H0);

    if (fork) cudaStreamWaitEvent(0, evJoin, 0);   // CSR ready before aggregation
    aggregate_kernel<128, true, true><<<aggBlocks, 256>>>(
        hw16_ptr, b1, nullptr, h16_ptr, N);

    // 5) layer 2
    gemm_h16_kernel<128><<<gemmBlocks, 256, SMEM_L128>>>(
        h16_ptr, bh_2, hw16_ptr, N, H0);
    aggregate_kernel<128, true, true><<<aggBlocks, 256>>>(
        hw16_ptr, b2, nullptr, h16_ptr, N);

    // 6) layer 3 (out dim 64, no relu) -> d_out fp32
    gemm_h16_kernel<64><<<gemmBlocks, 256, SMEM_L64>>>(
        h16_ptr, bh_3, hw16_ptr, N, H0);
    aggregate_kernel<64, false, false><<<aggBlocks, 256>>>(
        hw16_ptr, b3, (float*)d_out, nullptr, N);
}